// round 1
// baseline (speedup 1.0000x reference)
#include <cuda_runtime.h>
#include <math.h>

#define B_  8
#define N_  4096
#define K_  8
#define D_  256
#define CH_ 32
#define NC_ 128
#define LOGCONST (-235.24826450320013f)

// ---------------- scratch (device globals; no allocations) ----------------
__device__ float  g_Wt  [D_ * 2 * D_];        // [256][512]  (Wk^T | Wv^T)
__device__ float2 g_lnst[B_ * N_];            // per-row (mean, rstd)
__device__ float  g_keys[B_ * N_ * D_];
__device__ float  g_vals[B_ * N_ * D_];
__device__ float  g_gll [B_ * N_ * K_];
__device__ float  g_attn[B_ * N_ * K_];
__device__ float  g_q   [B_ * K_ * D_];
__device__ float  g_u   [B_ * K_ * D_];
__device__ float  g_w   [B_ * K_ * D_];
__device__ float  g_sig [B_ * K_ * D_];
__device__ float  g_mu  [B_ * K_ * D_];
__device__ float  g_c1  [B_ * K_];
__device__ float  g_mx  [B_ * K_];
__device__ float  g_di  [B_ * K_];
__device__ float  g_part[B_ * CH_ * K_ * D_]; // partial (k,d) sums per n-chunk

// ---------------- W transpose: g_Wt[e][j] = (j<256? Wk[j][e] : Wv[j-256][e])
__global__ void k_transposeW(const float* __restrict__ Wk, const float* __restrict__ Wv) {
    int gid = blockIdx.x * blockDim.x + threadIdx.x;   // 0 .. 131071
    int j = gid & 511;
    int e = gid >> 9;
    float v = (j < 256) ? Wk[j * D_ + e] : Wv[(j - 256) * D_ + e];
    g_Wt[e * 512 + j] = v;
}

// ---------------- LayerNorm row stats ----------------
__global__ void k_lnstats(const float* __restrict__ emb) {
    int warp = threadIdx.x >> 5;
    int lane = threadIdx.x & 31;
    int row  = blockIdx.x * 8 + warp;                  // 0 .. 32767
    const float* base = emb + (size_t)row * D_;
    float s = 0.f, sq = 0.f;
#pragma unroll
    for (int j = 0; j < 8; j++) {
        float v = base[lane + 32 * j];
        s += v;
        sq = fmaf(v, v, sq);
    }
#pragma unroll
    for (int o = 16; o; o >>= 1) {
        s  += __shfl_xor_sync(0xffffffffu, s,  o);
        sq += __shfl_xor_sync(0xffffffffu, sq, o);
    }
    if (lane == 0) {
        float mean = s * (1.0f / D_);
        float var  = sq * (1.0f / D_) - mean * mean;
        float rstd = 1.0f / sqrtf(var + 1e-5f);
        g_lnst[row] = make_float2(mean, rstd);
    }
}

// ---------------- fused LN + SGEMM: [32768,256] @ [256,512] -> keys|values ----
__global__ __launch_bounds__(256, 2) void k_gemm(const float* __restrict__ emb,
                                                 const float* __restrict__ lnsc,
                                                 const float* __restrict__ lnb) {
    __shared__ float As[2][16][128];
    __shared__ float Bs[2][16][128];
    const int tid = threadIdx.x;
    const int m0  = blockIdx.x * 128;
    const int n0  = blockIdx.y * 128;
    const int tx  = tid & 15, ty = tid >> 4;

    const int aRow0 = tid >> 2;          // 0..63
    const int aRow1 = aRow0 + 64;
    const int aE    = (tid & 3) * 4;     // 0,4,8,12
    const int gr0   = m0 + aRow0, gr1 = m0 + aRow1;
    const float2 st0 = g_lnst[gr0];
    const float2 st1 = g_lnst[gr1];
    const int bE = tid >> 5;             // 0..7
    const int bJ = (tid & 31) * 4;

    float acc[8][8];
#pragma unroll
    for (int i = 0; i < 8; i++)
#pragma unroll
        for (int j = 0; j < 8; j++) acc[i][j] = 0.f;

    auto load = [&](int buf, int k0) {
        float4 sc = *(const float4*)&lnsc[k0 + aE];
        float4 bi = *(const float4*)&lnb[k0 + aE];
        float4 a0 = *(const float4*)&emb[(size_t)gr0 * D_ + k0 + aE];
        float4 a1 = *(const float4*)&emb[(size_t)gr1 * D_ + k0 + aE];
        As[buf][aE + 0][aRow0] = (a0.x - st0.x) * st0.y * sc.x + bi.x;
        As[buf][aE + 1][aRow0] = (a0.y - st0.x) * st0.y * sc.y + bi.y;
        As[buf][aE + 2][aRow0] = (a0.z - st0.x) * st0.y * sc.z + bi.z;
        As[buf][aE + 3][aRow0] = (a0.w - st0.x) * st0.y * sc.w + bi.w;
        As[buf][aE + 0][aRow1] = (a1.x - st1.x) * st1.y * sc.x + bi.x;
        As[buf][aE + 1][aRow1] = (a1.y - st1.x) * st1.y * sc.y + bi.y;
        As[buf][aE + 2][aRow1] = (a1.z - st1.x) * st1.y * sc.z + bi.z;
        As[buf][aE + 3][aRow1] = (a1.w - st1.x) * st1.y * sc.w + bi.w;
        float4 b0 = *(const float4*)&g_Wt[(k0 + bE) * 512 + n0 + bJ];
        float4 b1 = *(const float4*)&g_Wt[(k0 + bE + 8) * 512 + n0 + bJ];
        *(float4*)&Bs[buf][bE][bJ]     = b0;
        *(float4*)&Bs[buf][bE + 8][bJ] = b1;
    };

    load(0, 0);
    __syncthreads();
#pragma unroll
    for (int s = 0; s < 16; s++) {
        if (s + 1 < 16) load((s + 1) & 1, (s + 1) * 16);
        int buf = s & 1;
#pragma unroll
        for (int kk = 0; kk < 16; kk++) {
            float4 a0 = *(const float4*)&As[buf][kk][ty * 8];
            float4 a1 = *(const float4*)&As[buf][kk][ty * 8 + 4];
            float4 b0 = *(const float4*)&Bs[buf][kk][tx * 8];
            float4 b1 = *(const float4*)&Bs[buf][kk][tx * 8 + 4];
            float av[8] = {a0.x, a0.y, a0.z, a0.w, a1.x, a1.y, a1.z, a1.w};
            float bv[8] = {b0.x, b0.y, b0.z, b0.w, b1.x, b1.y, b1.z, b1.w};
#pragma unroll
            for (int i = 0; i < 8; i++)
#pragma unroll
                for (int j = 0; j < 8; j++) acc[i][j] = fmaf(av[i], bv[j], acc[i][j]);
        }
        __syncthreads();
    }

#pragma unroll
    for (int i = 0; i < 8; i++) {
        int r = m0 + ty * 8 + i;
        float4 v0 = make_float4(acc[i][0], acc[i][1], acc[i][2], acc[i][3]);
        float4 v1 = make_float4(acc[i][4], acc[i][5], acc[i][6], acc[i][7]);
        int c = n0 + tx * 8;
        if (n0 < 256) {
            *(float4*)&g_keys[(size_t)r * D_ + c]     = v0;
            *(float4*)&g_keys[(size_t)r * D_ + c + 4] = v1;
        } else {
            *(float4*)&g_vals[(size_t)r * D_ + c - 256] = v0;
            *(float4*)&g_vals[(size_t)r * D_ + c - 252] = v1;
        }
    }
}

// ---------------- slots + queries (constant across iterations) ----------------
__global__ void k_slots_q(const float* __restrict__ smu, const float* __restrict__ sls,
                          const float* __restrict__ ni,  const float* __restrict__ Wq) {
    int k = blockIdx.x, b = blockIdx.y, d = threadIdx.x;
    __shared__ float ss[D_];
    float sg   = expf(sls[k * D_ + d]);
    float slot = smu[k * D_ + d] + sg * ni[(b * K_ + k) * D_ + d];
    ss[d] = slot;
    g_sig[(b * K_ + k) * D_ + d] = sg;
    __syncthreads();
    const float* wr = Wq + (size_t)d * D_;
    float q = 0.f;
#pragma unroll 4
    for (int e = 0; e < D_; e += 4) {
        float4 w4 = *(const float4*)&wr[e];
        q = fmaf(ss[e + 0], w4.x, q);
        q = fmaf(ss[e + 1], w4.y, q);
        q = fmaf(ss[e + 2], w4.z, q);
        q = fmaf(ss[e + 3], w4.w, q);
    }
    g_q[(b * K_ + k) * D_ + d] = q;
}

// ---------------- per-iteration prep: w, u, c1 ----------------
__global__ void k_prep() {
    int k = blockIdx.x, b = blockIdx.y, d = threadIdx.x;
    int idx = (b * K_ + k) * D_ + d;
    float sg = g_sig[idx];
    float w  = 1.0f / (fmaf(sg, sg, 1e-8f));
    float q  = g_q[idx];
    g_w[idx] = w;
    g_u[idx] = q * w;
    float lv = logf(fabsf(sg) + 1e-8f);
    float qq = q * q * w;
    __shared__ float r1[D_], r2[D_];
    r1[d] = lv; r2[d] = qq;
    __syncthreads();
    for (int o = 128; o; o >>= 1) {
        if (d < o) { r1[d] += r1[d + o]; r2[d] += r2[d + o]; }
        __syncthreads();
    }
    if (d == 0) g_c1[b * K_ + k] = LOGCONST - 0.5f * r1[0] - 0.5f * r2[0];
}

// ---------------- gll: per (b,n): c1 + keys.u - 0.5 keys^2 . w, clipped ------
__global__ __launch_bounds__(256) void k_gll() {
    const int b  = blockIdx.y;
    const int n0 = blockIdx.x * 64;
    const int tid = threadIdx.x;
    const int wid = tid >> 5, lane = tid & 31;
    __shared__ float su[K_][D_];
    __shared__ float swm[K_][D_];
    __shared__ float sc1[K_];
#pragma unroll
    for (int i = 0; i < 8; i++) {
        int f = tid + i * 256;
        int k = f >> 8, d = f & 255;
        su[k][d]  = g_u[(b * K_ + k) * D_ + d];
        swm[k][d] = -0.5f * g_w[(b * K_ + k) * D_ + d];
    }
    if (tid < K_) sc1[tid] = g_c1[b * K_ + tid];
    __syncthreads();

    for (int r = 0; r < 8; r++) {
        int n = n0 + wid * 8 + r;
        const float* kr = g_keys + ((size_t)(b * N_ + n)) * D_;
        float acc[K_];
#pragma unroll
        for (int k = 0; k < K_; k++) acc[k] = 0.f;
#pragma unroll
        for (int j = 0; j < 8; j++) {
            int   dd = lane + 32 * j;
            float kv = kr[dd];
            float k2 = kv * kv;
#pragma unroll
            for (int k = 0; k < K_; k++) {
                acc[k] = fmaf(kv, su[k][dd], acc[k]);
                acc[k] = fmaf(k2, swm[k][dd], acc[k]);
            }
        }
#pragma unroll
        for (int o = 16; o; o >>= 1)
#pragma unroll
            for (int k = 0; k < K_; k++) acc[k] += __shfl_xor_sync(0xffffffffu, acc[k], o);
        if (lane == 0) {
#pragma unroll
            for (int k = 0; k < K_; k++) {
                float g = sc1[k] + acc[k];
                g = fminf(fmaxf(g, -10000.f), 10000.f);
                g_gll[((size_t)(b * N_ + n)) * K_ + k] = g;
            }
        }
    }
}

// ---------------- softmax reduce over N per (b,k) ----------------
__global__ void k_softmax() {
    int bk = blockIdx.x;
    int b = bk >> 3, k = bk & 7;
    int tid = threadIdx.x;
    __shared__ float red[256];
    float v[16];
    float mx = -3.4e38f;
#pragma unroll
    for (int i = 0; i < 16; i++) {
        int n = tid + (i << 8);
        v[i] = g_gll[((size_t)(b * N_ + n)) * K_ + k];
        mx = fmaxf(mx, v[i]);
    }
    red[tid] = mx; __syncthreads();
    for (int o = 128; o; o >>= 1) { if (tid < o) red[tid] = fmaxf(red[tid], red[tid + o]); __syncthreads(); }
    mx = red[0]; __syncthreads();
    float s = 0.f;
#pragma unroll
    for (int i = 0; i < 16; i++) s += expf(v[i] - mx);
    red[tid] = s; __syncthreads();
    for (int o = 128; o; o >>= 1) { if (tid < o) red[tid] += red[tid + o]; __syncthreads(); }
    if (tid == 0) { g_mx[bk] = mx; g_di[bk] = 1.0f / red[0]; }
}

// ---------------- attn + partial mu; optional transposed attn output ----------
__global__ __launch_bounds__(256) void k_mu(float* __restrict__ outA, int last) {
    int ch = blockIdx.x, b = blockIdx.y;
    int n0 = ch * NC_;
    int tid = threadIdx.x;
    __shared__ __align__(16) float sa[NC_][K_];
    __shared__ float sm[K_], sd[K_];
    if (tid < K_) { sm[tid] = g_mx[b * K_ + tid]; sd[tid] = g_di[b * K_ + tid]; }
    __syncthreads();
#pragma unroll
    for (int i = 0; i < 4; i++) {
        int idx = tid + i * 256;            // 0..1023 -> (nl, k)
        int nl = idx >> 3, k = idx & 7;
        float g = g_gll[((size_t)(b * N_ + n0 + nl)) * K_ + k];
        float a = expf(g - sm[k]) * sd[k];
        sa[nl][k] = a;
        g_attn[((size_t)(b * N_ + n0 + nl)) * K_ + k] = a;
    }
    __syncthreads();
    if (last && tid < NC_) {
#pragma unroll
        for (int k = 0; k < K_; k++)
            outA[((size_t)(b * K_ + k)) * N_ + n0 + tid] = sa[tid][k];
    }
    int d = tid;
    float acc[K_];
#pragma unroll
    for (int k = 0; k < K_; k++) acc[k] = 0.f;
    const float* vb = g_vals + ((size_t)(b * N_ + n0)) * D_ + d;
    for (int nl = 0; nl < NC_; nl++) {
        float vv = vb[(size_t)nl * D_];
        float4 a0 = *(const float4*)&sa[nl][0];
        float4 a1 = *(const float4*)&sa[nl][4];
        acc[0] = fmaf(a0.x, vv, acc[0]); acc[1] = fmaf(a0.y, vv, acc[1]);
        acc[2] = fmaf(a0.z, vv, acc[2]); acc[3] = fmaf(a0.w, vv, acc[3]);
        acc[4] = fmaf(a1.x, vv, acc[4]); acc[5] = fmaf(a1.y, vv, acc[5]);
        acc[6] = fmaf(a1.z, vv, acc[6]); acc[7] = fmaf(a1.w, vv, acc[7]);
    }
#pragma unroll
    for (int k = 0; k < K_; k++)
        g_part[(((size_t)(b * CH_ + ch)) * K_ + k) * D_ + d] = acc[k];
}

// ---------------- reduce partials -> g_mu (flag 0) or g_sig (flag 1) ----------
__global__ void k_redpart(int flag) {
    int k = blockIdx.x, b = blockIdx.y, d = threadIdx.x;
    float s = 0.f;
#pragma unroll 8
    for (int c = 0; c < CH_; c++)
        s += g_part[(((size_t)(b * CH_ + c)) * K_ + k) * D_ + d];
    if (flag) g_sig[(b * K_ + k) * D_ + d] = s;
    else      g_mu [(b * K_ + k) * D_ + d] = s;
}

// ---------------- partial sigma: sum attn*(v-mu)^2 ----------------
__global__ __launch_bounds__(256) void k_sigpass() {
    int ch = blockIdx.x, b = blockIdx.y;
    int n0 = ch * NC_;
    int tid = threadIdx.x;
    __shared__ __align__(16) float sa[NC_][K_];
#pragma unroll
    for (int i = 0; i < 4; i++) {
        int idx = tid + i * 256;
        int nl = idx >> 3, k = idx & 7;
        sa[nl][k] = g_attn[((size_t)(b * N_ + n0 + nl)) * K_ + k];
    }
    int d = tid;
    float mu8[K_];
#pragma unroll
    for (int k = 0; k < K_; k++) mu8[k] = g_mu[(b * K_ + k) * D_ + d];
    __syncthreads();
    float acc[K_];
#pragma unroll
    for (int k = 0; k < K_; k++) acc[k] = 0.f;
    const float* vb = g_vals + ((size_t)(b * N_ + n0)) * D_ + d;
    for (int nl = 0; nl < NC_; nl++) {
        float vv = vb[(size_t)nl * D_];
        float4 a0 = *(const float4*)&sa[nl][0];
        float4 a1 = *(const float4*)&sa[nl][4];
        float t;
        t = vv - mu8[0]; acc[0] = fmaf(a0.x, t * t, acc[0]);
        t = vv - mu8[1]; acc[1] = fmaf(a0.y, t * t, acc[1]);
        t = vv - mu8[2]; acc[2] = fmaf(a0.z, t * t, acc[2]);
        t = vv - mu8[3]; acc[3] = fmaf(a0.w, t * t, acc[3]);
        t = vv - mu8[4]; acc[4] = fmaf(a1.x, t * t, acc[4]);
        t = vv - mu8[5]; acc[5] = fmaf(a1.y, t * t, acc[5]);
        t = vv - mu8[6]; acc[6] = fmaf(a1.z, t * t, acc[6]);
        t = vv - mu8[7]; acc[7] = fmaf(a1.w, t * t, acc[7]);
    }
#pragma unroll
    for (int k = 0; k < K_; k++)
        g_part[(((size_t)(b * CH_ + ch)) * K_ + k) * D_ + d] = acc[k];
}

// ---------------- final: slots_out = mu + max(|sigma|,eps)*noise_final --------
__global__ void k_final(const float* __restrict__ nf, float* __restrict__ out) {
    int k = blockIdx.x, b = blockIdx.y, d = threadIdx.x;
    int idx = (b * K_ + k) * D_ + d;
    out[idx] = g_mu[idx] + fmaxf(fabsf(g_sig[idx]), 1e-8f) * nf[idx];
}

// ---------------------------------------------------------------------------
extern "C" void kernel_launch(void* const* d_in, const int* in_sizes, int n_in,
                              void* d_out, int out_size) {
    const float* emb  = (const float*)d_in[0];
    const float* smu  = (const float*)d_in[1];
    const float* sls  = (const float*)d_in[2];
    const float* Wq   = (const float*)d_in[4];
    const float* Wk   = (const float*)d_in[5];
    const float* Wv   = (const float*)d_in[6];
    const float* lnsc = (const float*)d_in[7];
    const float* lnb  = (const float*)d_in[8];
    const float* ni   = (const float*)d_in[9];
    const float* nf   = (const float*)d_in[10];
    float* out      = (float*)d_out;
    float* out_attn = out + B_ * K_ * D_;

    k_transposeW<<<256, 512>>>(Wk, Wv);
    k_lnstats<<<N_ * B_ / 8, 256>>>(emb);
    k_gemm<<<dim3(B_ * N_ / 128, 4), 256>>>(emb, lnsc, lnb);
    k_slots_q<<<dim3(K_, B_), 256>>>(smu, sls, ni, Wq);

    const int iters = 3;
    for (int it = 0; it < iters; it++) {
        int last = (it == iters - 1) ? 1 : 0;
        k_prep<<<dim3(K_, B_), 256>>>();
        k_gll<<<dim3(N_ / 64, B_), 256>>>();
        k_softmax<<<B_ * K_, 256>>>();
        k_mu<<<dim3(CH_, B_), 256>>>(out_attn, last);
        k_redpart<<<dim3(K_, B_), 256>>>(0);
        k_sigpass<<<dim3(CH_, B_), 256>>>();
        k_redpart<<<dim3(K_, B_), 256>>>(1);
    }
    k_final<<<dim3(K_, B_), 256>>>(nf, out);
}

// round 5
// speedup vs baseline: 1.0073x; 1.0073x over previous
#include <cuda_runtime.h>
#include <math.h>

#define B_  8
#define N_  4096
#define K_  8
#define D_  256
#define CH_ 32
#define NC_ 128
#define LOGCONST (-235.24826450320013f)

// ---------------- scratch (device globals; no allocations) ----------------
__device__ float  g_Wt  [D_ * 2 * D_];        // [256][512]  (Wk^T | Wv^T)
__device__ float2 g_lnst[B_ * N_];            // per-row (mean, rstd)
__device__ float  g_keys[B_ * N_ * D_];
__device__ float  g_vals[B_ * N_ * D_];
__device__ float  g_gll [B_ * N_ * K_];
__device__ float  g_attn[B_ * N_ * K_];
__device__ float  g_q   [B_ * K_ * D_];
__device__ float  g_u   [B_ * K_ * D_];
__device__ float  g_w   [B_ * K_ * D_];
__device__ float  g_sig [B_ * K_ * D_];
__device__ float  g_mu  [B_ * K_ * D_];
__device__ float  g_c1  [B_ * K_];
__device__ float  g_mx  [B_ * K_];
__device__ float  g_di  [B_ * K_];
__device__ float  g_part[B_ * CH_ * K_ * D_]; // partial (k,d) sums per n-chunk

// ---------------- W transpose: g_Wt[e][j] = (j<256? Wk[j][e] : Wv[j-256][e])
__global__ void k_transposeW(const float* __restrict__ Wk, const float* __restrict__ Wv) {
    int gid = blockIdx.x * blockDim.x + threadIdx.x;   // 0 .. 131071
    int j = gid & 511;
    int e = gid >> 9;
    float v = (j < 256) ? Wk[j * D_ + e] : Wv[(j - 256) * D_ + e];
    g_Wt[e * 512 + j] = v;
}

// ---------------- LayerNorm row stats ----------------
__global__ void k_lnstats(const float* __restrict__ emb) {
    int warp = threadIdx.x >> 5;
    int lane = threadIdx.x & 31;
    int row  = blockIdx.x * 8 + warp;                  // 0 .. 32767
    const float* base = emb + (size_t)row * D_;
    float s = 0.f, sq = 0.f;
#pragma unroll
    for (int j = 0; j < 8; j++) {
        float v = base[lane + 32 * j];
        s += v;
        sq = fmaf(v, v, sq);
    }
#pragma unroll
    for (int o = 16; o; o >>= 1) {
        s  += __shfl_xor_sync(0xffffffffu, s,  o);
        sq += __shfl_xor_sync(0xffffffffu, sq, o);
    }
    if (lane == 0) {
        float mean = s * (1.0f / D_);
        float var  = sq * (1.0f / D_) - mean * mean;
        float rstd = 1.0f / sqrtf(var + 1e-5f);
        g_lnst[row] = make_float2(mean, rstd);
    }
}

// ---------------- fused LN + SGEMM: [32768,256] @ [256,512] -> keys|values ----
__global__ __launch_bounds__(256, 2) void k_gemm(const float* __restrict__ emb,
                                                 const float* __restrict__ lnsc,
                                                 const float* __restrict__ lnb) {
    __shared__ float As[2][16][128];
    __shared__ float Bs[2][16][128];
    const int tid = threadIdx.x;
    const int m0  = blockIdx.x * 128;
    const int n0  = blockIdx.y * 128;
    const int tx  = tid & 15, ty = tid >> 4;

    const int aRow0 = tid >> 2;          // 0..63
    const int aRow1 = aRow0 + 64;
    const int aE    = (tid & 3) * 4;     // 0,4,8,12
    const int gr0   = m0 + aRow0, gr1 = m0 + aRow1;
    const float2 st0 = g_lnst[gr0];
    const float2 st1 = g_lnst[gr1];
    const int bE = tid >> 5;             // 0..7
    const int bJ = (tid & 31) * 4;

    float acc[8][8];
#pragma unroll
    for (int i = 0; i < 8; i++)
#pragma unroll
        for (int j = 0; j < 8; j++) acc[i][j] = 0.f;

    auto load = [&](int buf, int k0) {
        float4 sc = *(const float4*)&lnsc[k0 + aE];
        float4 bi = *(const float4*)&lnb[k0 + aE];
        float4 a0 = *(const float4*)&emb[(size_t)gr0 * D_ + k0 + aE];
        float4 a1 = *(const float4*)&emb[(size_t)gr1 * D_ + k0 + aE];
        As[buf][aE + 0][aRow0] = (a0.x - st0.x) * st0.y * sc.x + bi.x;
        As[buf][aE + 1][aRow0] = (a0.y - st0.x) * st0.y * sc.y + bi.y;
        As[buf][aE + 2][aRow0] = (a0.z - st0.x) * st0.y * sc.z + bi.z;
        As[buf][aE + 3][aRow0] = (a0.w - st0.x) * st0.y * sc.w + bi.w;
        As[buf][aE + 0][aRow1] = (a1.x - st1.x) * st1.y * sc.x + bi.x;
        As[buf][aE + 1][aRow1] = (a1.y - st1.x) * st1.y * sc.y + bi.y;
        As[buf][aE + 2][aRow1] = (a1.z - st1.x) * st1.y * sc.z + bi.z;
        As[buf][aE + 3][aRow1] = (a1.w - st1.x) * st1.y * sc.w + bi.w;
        float4 b0 = *(const float4*)&g_Wt[(k0 + bE) * 512 + n0 + bJ];
        float4 b1 = *(const float4*)&g_Wt[(k0 + bE + 8) * 512 + n0 + bJ];
        *(float4*)&Bs[buf][bE][bJ]     = b0;
        *(float4*)&Bs[buf][bE + 8][bJ] = b1;
    };

    load(0, 0);
    __syncthreads();
#pragma unroll
    for (int s = 0; s < 16; s++) {
        if (s + 1 < 16) load((s + 1) & 1, (s + 1) * 16);
        int buf = s & 1;
#pragma unroll
        for (int kk = 0; kk < 16; kk++) {
            float4 a0 = *(const float4*)&As[buf][kk][ty * 8];
            float4 a1 = *(const float4*)&As[buf][kk][ty * 8 + 4];
            float4 b0 = *(const float4*)&Bs[buf][kk][tx * 8];
            float4 b1 = *(const float4*)&Bs[buf][kk][tx * 8 + 4];
            float av[8] = {a0.x, a0.y, a0.z, a0.w, a1.x, a1.y, a1.z, a1.w};
            float bv[8] = {b0.x, b0.y, b0.z, b0.w, b1.x, b1.y, b1.z, b1.w};
#pragma unroll
            for (int i = 0; i < 8; i++)
#pragma unroll
                for (int j = 0; j < 8; j++) acc[i][j] = fmaf(av[i], bv[j], acc[i][j]);
        }
        __syncthreads();
    }

#pragma unroll
    for (int i = 0; i < 8; i++) {
        int r = m0 + ty * 8 + i;
        float4 v0 = make_float4(acc[i][0], acc[i][1], acc[i][2], acc[i][3]);
        float4 v1 = make_float4(acc[i][4], acc[i][5], acc[i][6], acc[i][7]);
        int c = n0 + tx * 8;
        if (n0 < 256) {
            *(float4*)&g_keys[(size_t)r * D_ + c]     = v0;
            *(float4*)&g_keys[(size_t)r * D_ + c + 4] = v1;
        } else {
            *(float4*)&g_vals[(size_t)r * D_ + c - 256] = v0;
            *(float4*)&g_vals[(size_t)r * D_ + c - 252] = v1;
        }
    }
}

// ---------------- slots + queries (constant across iterations) ----------------
__global__ void k_slots_q(const float* __restrict__ smu, const float* __restrict__ sls,
                          const float* __restrict__ ni,  const float* __restrict__ Wq) {
    int k = blockIdx.x, b = blockIdx.y, d = threadIdx.x;
    __shared__ float ss[D_];
    float sg   = expf(sls[k * D_ + d]);
    float slot = smu[k * D_ + d] + sg * ni[(b * K_ + k) * D_ + d];
    ss[d] = slot;
    g_sig[(b * K_ + k) * D_ + d] = sg;
    __syncthreads();
    const float* wr = Wq + (size_t)d * D_;
    float q = 0.f;
#pragma unroll 4
    for (int e = 0; e < D_; e += 4) {
        float4 w4 = *(const float4*)&wr[e];
        q = fmaf(ss[e + 0], w4.x, q);
        q = fmaf(ss[e + 1], w4.y, q);
        q = fmaf(ss[e + 2], w4.z, q);
        q = fmaf(ss[e + 3], w4.w, q);
    }
    g_q[(b * K_ + k) * D_ + d] = q;
}

// ---------------- per-iteration prep: w, u, c1 ----------------
__global__ void k_prep() {
    int k = blockIdx.x, b = blockIdx.y, d = threadIdx.x;
    int idx = (b * K_ + k) * D_ + d;
    float sg = g_sig[idx];
    float w  = 1.0f / (fmaf(sg, sg, 1e-8f));
    float q  = g_q[idx];
    g_w[idx] = w;
    g_u[idx] = q * w;
    float lv = logf(fabsf(sg) + 1e-8f);
    float qq = q * q * w;
    __shared__ float r1[D_], r2[D_];
    r1[d] = lv; r2[d] = qq;
    __syncthreads();
    for (int o = 128; o; o >>= 1) {
        if (d < o) { r1[d] += r1[d + o]; r2[d] += r2[d + o]; }
        __syncthreads();
    }
    if (d == 0) g_c1[b * K_ + k] = LOGCONST - 0.5f * r1[0] - 0.5f * r2[0];
}

// ---------------- gll: per (b,n): c1 + keys.u - 0.5 keys^2 . w, clipped ------
__global__ __launch_bounds__(256) void k_gll() {
    const int b  = blockIdx.y;
    const int n0 = blockIdx.x * 64;
    const int tid = threadIdx.x;
    const int wid = tid >> 5, lane = tid & 31;
    __shared__ float su[K_][D_];
    __shared__ float swm[K_][D_];
    __shared__ float sc1[K_];
#pragma unroll
    for (int i = 0; i < 8; i++) {
        int f = tid + i * 256;
        int k = f >> 8, d = f & 255;
        su[k][d]  = g_u[(b * K_ + k) * D_ + d];
        swm[k][d] = -0.5f * g_w[(b * K_ + k) * D_ + d];
    }
    if (tid < K_) sc1[tid] = g_c1[b * K_ + tid];
    __syncthreads();

    for (int r = 0; r < 8; r++) {
        int n = n0 + wid * 8 + r;
        const float* kr = g_keys + ((size_t)(b * N_ + n)) * D_;
        float acc[K_];
#pragma unroll
        for (int k = 0; k < K_; k++) acc[k] = 0.f;
#pragma unroll
        for (int j = 0; j < 8; j++) {
            int   dd = lane + 32 * j;
            float kv = kr[dd];
            float k2 = kv * kv;
#pragma unroll
            for (int k = 0; k < K_; k++) {
                acc[k] = fmaf(kv, su[k][dd], acc[k]);
                acc[k] = fmaf(k2, swm[k][dd], acc[k]);
            }
        }
#pragma unroll
        for (int o = 16; o; o >>= 1)
#pragma unroll
            for (int k = 0; k < K_; k++) acc[k] += __shfl_xor_sync(0xffffffffu, acc[k], o);
        if (lane == 0) {
#pragma unroll
            for (int k = 0; k < K_; k++) {
                float g = sc1[k] + acc[k];
                g = fminf(fmaxf(g, -10000.f), 10000.f);
                g_gll[((size_t)(b * N_ + n)) * K_ + k] = g;
            }
        }
    }
}

// ---------------- softmax reduce over N per (b,k) ----------------
__global__ void k_softmax() {
    int bk = blockIdx.x;
    int b = bk >> 3, k = bk & 7;
    int tid = threadIdx.x;
    __shared__ float red[256];
    float v[16];
    float mx = -3.4e38f;
#pragma unroll
    for (int i = 0; i < 16; i++) {
        int n = tid + (i << 8);
        v[i] = g_gll[((size_t)(b * N_ + n)) * K_ + k];
        mx = fmaxf(mx, v[i]);
    }
    red[tid] = mx; __syncthreads();
    for (int o = 128; o; o >>= 1) { if (tid < o) red[tid] = fmaxf(red[tid], red[tid + o]); __syncthreads(); }
    mx = red[0]; __syncthreads();
    float s = 0.f;
#pragma unroll
    for (int i = 0; i < 16; i++) s += expf(v[i] - mx);
    red[tid] = s; __syncthreads();
    for (int o = 128; o; o >>= 1) { if (tid < o) red[tid] += red[tid + o]; __syncthreads(); }
    if (tid == 0) { g_mx[bk] = mx; g_di[bk] = 1.0f / red[0]; }
}

// ---------------- attn + partial mu; optional transposed attn output ----------
__global__ __launch_bounds__(256) void k_mu(float* __restrict__ outA, int last) {
    int ch = blockIdx.x, b = blockIdx.y;
    int n0 = ch * NC_;
    int tid = threadIdx.x;
    __shared__ __align__(16) float sa[NC_][K_];
    __shared__ float sm[K_], sd[K_];
    if (tid < K_) { sm[tid] = g_mx[b * K_ + tid]; sd[tid] = g_di[b * K_ + tid]; }
    __syncthreads();
#pragma unroll
    for (int i = 0; i < 4; i++) {
        int idx = tid + i * 256;            // 0..1023 -> (nl, k)
        int nl = idx >> 3, k = idx & 7;
        float g = g_gll[((size_t)(b * N_ + n0 + nl)) * K_ + k];
        float a = expf(g - sm[k]) * sd[k];
        sa[nl][k] = a;
        g_attn[((size_t)(b * N_ + n0 + nl)) * K_ + k] = a;
    }
    __syncthreads();
    if (last && tid < NC_) {
#pragma unroll
        for (int k = 0; k < K_; k++)
            outA[((size_t)(b * K_ + k)) * N_ + n0 + tid] = sa[tid][k];
    }
    int d = tid;
    float acc[K_];
#pragma unroll
    for (int k = 0; k < K_; k++) acc[k] = 0.f;
    const float* vb = g_vals + ((size_t)(b * N_ + n0)) * D_ + d;
    for (int nl = 0; nl < NC_; nl++) {
        float vv = vb[(size_t)nl * D_];
        float4 a0 = *(const float4*)&sa[nl][0];
        float4 a1 = *(const float4*)&sa[nl][4];
        acc[0] = fmaf(a0.x, vv, acc[0]); acc[1] = fmaf(a0.y, vv, acc[1]);
        acc[2] = fmaf(a0.z, vv, acc[2]); acc[3] = fmaf(a0.w, vv, acc[3]);
        acc[4] = fmaf(a1.x, vv, acc[4]); acc[5] = fmaf(a1.y, vv, acc[5]);
        acc[6] = fmaf(a1.z, vv, acc[6]); acc[7] = fmaf(a1.w, vv, acc[7]);
    }
#pragma unroll
    for (int k = 0; k < K_; k++)
        g_part[(((size_t)(b * CH_ + ch)) * K_ + k) * D_ + d] = acc[k];
}

// ---------------- reduce partials -> g_mu (flag 0) or g_sig (flag 1) ----------
__global__ void k_redpart(int flag) {
    int k = blockIdx.x, b = blockIdx.y, d = threadIdx.x;
    float s = 0.f;
#pragma unroll 8
    for (int c = 0; c < CH_; c++)
        s += g_part[(((size_t)(b * CH_ + c)) * K_ + k) * D_ + d];
    if (flag) g_sig[(b * K_ + k) * D_ + d] = s;
    else      g_mu [(b * K_ + k) * D_ + d] = s;
}

// ---------------- partial sigma: sum attn*(v-mu)^2 ----------------
__global__ __launch_bounds__(256) void k_sigpass() {
    int ch = blockIdx.x, b = blockIdx.y;
    int n0 = ch * NC_;
    int tid = threadIdx.x;
    __shared__ __align__(16) float sa[NC_][K_];
#pragma unroll
    for (int i = 0; i < 4; i++) {
        int idx = tid + i * 256;
        int nl = idx >> 3, k = idx & 7;
        sa[nl][k] = g_attn[((size_t)(b * N_ + n0 + nl)) * K_ + k];
    }
    int d = tid;
    float mu8[K_];
#pragma unroll
    for (int k = 0; k < K_; k++) mu8[k] = g_mu[(b * K_ + k) * D_ + d];
    __syncthreads();
    float acc[K_];
#pragma unroll
    for (int k = 0; k < K_; k++) acc[k] = 0.f;
    const float* vb = g_vals + ((size_t)(b * N_ + n0)) * D_ + d;
    for (int nl = 0; nl < NC_; nl++) {
        float vv = vb[(size_t)nl * D_];
        float4 a0 = *(const float4*)&sa[nl][0];
        float4 a1 = *(const float4*)&sa[nl][4];
        float t;
        t = vv - mu8[0]; acc[0] = fmaf(a0.x, t * t, acc[0]);
        t = vv - mu8[1]; acc[1] = fmaf(a0.y, t * t, acc[1]);
        t = vv - mu8[2]; acc[2] = fmaf(a0.z, t * t, acc[2]);
        t = vv - mu8[3]; acc[3] = fmaf(a0.w, t * t, acc[3]);
        t = vv - mu8[4]; acc[4] = fmaf(a1.x, t * t, acc[4]);
        t = vv - mu8[5]; acc[5] = fmaf(a1.y, t * t, acc[5]);
        t = vv - mu8[6]; acc[6] = fmaf(a1.z, t * t, acc[6]);
        t = vv - mu8[7]; acc[7] = fmaf(a1.w, t * t, acc[7]);
    }
#pragma unroll
    for (int k = 0; k < K_; k++)
        g_part[(((size_t)(b * CH_ + ch)) * K_ + k) * D_ + d] = acc[k];
}

// ---------------- final: slots_out = mu + max(|sigma|,eps)*noise_final --------
__global__ void k_final(const float* __restrict__ nf, float* __restrict__ out) {
    int k = blockIdx.x, b = blockIdx.y, d = threadIdx.x;
    int idx = (b * K_ + k) * D_ + d;
    out[idx] = g_mu[idx] + fmaxf(fabsf(g_sig[idx]), 1e-8f) * nf[idx];
}

// ---------------------------------------------------------------------------
extern "C" void kernel_launch(void* const* d_in, const int* in_sizes, int n_in,
                              void* d_out, int out_size) {
    const float* emb  = (const float*)d_in[0];
    const float* smu  = (const float*)d_in[1];
    const float* sls  = (const float*)d_in[2];
    const float* Wq   = (const float*)d_in[4];
    const float* Wk   = (const float*)d_in[5];
    const float* Wv   = (const float*)d_in[6];
    const float* lnsc = (const float*)d_in[7];
    const float* lnb  = (const float*)d_in[8];
    const float* ni   = (const float*)d_in[9];
    const float* nf   = (const float*)d_in[10];
    float* out      = (float*)d_out;
    float* out_attn = out + B_ * K_ * D_;

    k_transposeW<<<256, 512>>>(Wk, Wv);
    k_lnstats<<<N_ * B_ / 8, 256>>>(emb);
    k_gemm<<<dim3(B_ * N_ / 128, 4), 256>>>(emb, lnsc, lnb);
    k_slots_q<<<dim3(K_, B_), 256>>>(smu, sls, ni, Wq);

    const int iters = 3;
    for (int it = 0; it < iters; it++) {
        int last = (it == iters - 1) ? 1 : 0;
        k_prep<<<dim3(K_, B_), 256>>>();
        k_gll<<<dim3(N_ / 64, B_), 256>>>();
        k_softmax<<<B_ * K_, 256>>>();
        k_mu<<<dim3(CH_, B_), 256>>>(out_attn, last);
        k_redpart<<<dim3(K_, B_), 256>>>(0);
        k_sigpass<<<dim3(CH_, B_), 256>>>();
        k_redpart<<<dim3(K_, B_), 256>>>(1);
    }
    k_final<<<dim3(K_, B_), 256>>>(nf, out);
}

// round 7
// speedup vs baseline: 1.3304x; 1.3207x over previous
#include <cuda_runtime.h>
#include <math.h>

typedef unsigned int u32;

#define B_  8
#define N_  4096
#define K_  8
#define D_  256
#define CH_ 32
#define NC_ 128
#define LOGCONST (-235.24826450320013f)

// ---------------- scratch ----------------
__device__ float2 g_lnst[B_ * N_];
__device__ float  g_keys[B_ * N_ * D_];
__device__ float  g_vals[B_ * N_ * D_];
__device__ float  g_gll [B_ * N_ * K_];
__device__ float  g_attn[B_ * N_ * K_];
__device__ float  g_q   [B_ * K_ * D_];
__device__ float  g_sig [B_ * K_ * D_];
__device__ float  g_mu  [B_ * K_ * D_];
__device__ float  g_mx  [B_ * K_];
__device__ float  g_di  [B_ * K_];
__device__ float  g_part[B_ * CH_ * K_ * D_];

// ---------------- LayerNorm row stats ----------------
__global__ void k_lnstats(const float* __restrict__ emb) {
    int warp = threadIdx.x >> 5, lane = threadIdx.x & 31;
    int row  = blockIdx.x * 8 + warp;
    const float* base = emb + (size_t)row * D_;
    float s = 0.f, sq = 0.f;
#pragma unroll
    for (int j = 0; j < 8; j++) {
        float v = base[lane + 32 * j];
        s += v;
        sq = fmaf(v, v, sq);
    }
#pragma unroll
    for (int o = 16; o; o >>= 1) {
        s  += __shfl_xor_sync(0xffffffffu, s,  o);
        sq += __shfl_xor_sync(0xffffffffu, sq, o);
    }
    if (lane == 0) {
        float mean = s * (1.0f / D_);
        float var  = sq * (1.0f / D_) - mean * mean;
        g_lnst[row] = make_float2(mean, 1.0f / sqrtf(var + 1e-5f));
    }
}

// ============ tf32x3 GEMM via mma.sync (sm_80+ PTX, no 'a' features) ============
__device__ __forceinline__ void mma8(float* c, const u32* a, const u32* b) {
    asm volatile(
        "mma.sync.aligned.m16n8k8.row.col.f32.tf32.tf32.f32 "
        "{%0,%1,%2,%3}, {%4,%5,%6,%7}, {%8,%9}, {%0,%1,%2,%3};"
        : "+f"(c[0]), "+f"(c[1]), "+f"(c[2]), "+f"(c[3])
        : "r"(a[0]), "r"(a[1]), "r"(a[2]), "r"(a[3]), "r"(b[0]), "r"(b[1]));
}
__device__ __forceinline__ u32 to_tf32(float x) {
    u32 r;
    asm("cvt.rna.tf32.f32 %0, %1;" : "=r"(r) : "f"(x));
    return r;
}

#define PADK 36
#define SMA (128 * PADK)
#define GEMM_SMEM (4 * SMA * 4)

__global__ __launch_bounds__(256) void k_gemm_mma(const float* __restrict__ emb,
                                                  const float* __restrict__ lnsc,
                                                  const float* __restrict__ lnb,
                                                  const float* __restrict__ Wk,
                                                  const float* __restrict__ Wv) {
    extern __shared__ float sh[];
    float* Ah = sh;
    float* Al = sh + SMA;
    float* Bh = sh + 2 * SMA;
    float* Bl = sh + 3 * SMA;
    const int tid = threadIdx.x, lane = tid & 31, wid = tid >> 5;
    const int m0 = blockIdx.x * 128;
    const int nq = blockIdx.y;                       // 0..3
    const float* Bsrc = (nq < 2) ? Wk : Wv;
    float* outp = (nq < 2) ? g_keys : g_vals;
    const int n0 = (nq & 1) * 128;
    const int wm = wid >> 2, wn = wid & 3;           // warp grid 2x4
    const int g = lane >> 2, tt = lane & 3;

    float acc[4][4][4];
#pragma unroll
    for (int i = 0; i < 4; i++)
#pragma unroll
        for (int j = 0; j < 4; j++)
#pragma unroll
            for (int r = 0; r < 4; r++) acc[i][j][r] = 0.f;

    for (int kc = 0; kc < 8; kc++) {
        const int k0 = kc * 32;
        if (kc) __syncthreads();
        // ---- A chunk 128x32, LN-fused, hi/lo split ----
#pragma unroll
        for (int i = 0; i < 4; i++) {
            int lin = tid + i * 256;
            int row = lin >> 3, sg = (lin & 7) * 4;
            float2 st = g_lnst[m0 + row];
            float4 a  = *(const float4*)&emb[(size_t)(m0 + row) * D_ + k0 + sg];
            float4 sc = *(const float4*)&lnsc[k0 + sg];
            float4 bi = *(const float4*)&lnb[k0 + sg];
            float x[4];
            x[0] = fmaf((a.x - st.x) * st.y, sc.x, bi.x);
            x[1] = fmaf((a.y - st.x) * st.y, sc.y, bi.y);
            x[2] = fmaf((a.z - st.x) * st.y, sc.z, bi.z);
            x[3] = fmaf((a.w - st.x) * st.y, sc.w, bi.w);
            u32 hb[4], lb[4];
#pragma unroll
            for (int j = 0; j < 4; j++) {
                hb[j] = __float_as_uint(x[j]) & 0xffffe000u;
                lb[j] = to_tf32(x[j] - __uint_as_float(hb[j]));
            }
            *(float4*)&Ah[row * PADK + sg] =
                make_float4(__uint_as_float(hb[0]), __uint_as_float(hb[1]),
                            __uint_as_float(hb[2]), __uint_as_float(hb[3]));
            *(float4*)&Al[row * PADK + sg] =
                make_float4(__uint_as_float(lb[0]), __uint_as_float(lb[1]),
                            __uint_as_float(lb[2]), __uint_as_float(lb[3]));
        }
        // ---- B chunk 128x32, hi/lo split ----
#pragma unroll
        for (int i = 0; i < 4; i++) {
            int lin = tid + i * 256;
            int row = lin >> 3, sg = (lin & 7) * 4;
            float4 a = *(const float4*)&Bsrc[(size_t)(n0 + row) * D_ + k0 + sg];
            float x[4] = {a.x, a.y, a.z, a.w};
            u32 hb[4], lb[4];
#pragma unroll
            for (int j = 0; j < 4; j++) {
                hb[j] = __float_as_uint(x[j]) & 0xffffe000u;
                lb[j] = to_tf32(x[j] - __uint_as_float(hb[j]));
            }
            *(float4*)&Bh[row * PADK + sg] =
                make_float4(__uint_as_float(hb[0]), __uint_as_float(hb[1]),
                            __uint_as_float(hb[2]), __uint_as_float(hb[3]));
            *(float4*)&Bl[row * PADK + sg] =
                make_float4(__uint_as_float(lb[0]), __uint_as_float(lb[1]),
                            __uint_as_float(lb[2]), __uint_as_float(lb[3]));
        }
        __syncthreads();

#pragma unroll
        for (int ks = 0; ks < 4; ks++) {
            const int kk = ks * 8;
            u32 ah[4][4], al[4][4], bh[4][2], bl[4][2];
#pragma unroll
            for (int mt = 0; mt < 4; mt++) {
                int r = wm * 64 + mt * 16;
                ah[mt][0] = __float_as_uint(Ah[(r + g    ) * PADK + kk + tt    ]);
                ah[mt][1] = __float_as_uint(Ah[(r + g + 8) * PADK + kk + tt    ]);
                ah[mt][2] = __float_as_uint(Ah[(r + g    ) * PADK + kk + tt + 4]);
                ah[mt][3] = __float_as_uint(Ah[(r + g + 8) * PADK + kk + tt + 4]);
                al[mt][0] = __float_as_uint(Al[(r + g    ) * PADK + kk + tt    ]);
                al[mt][1] = __float_as_uint(Al[(r + g + 8) * PADK + kk + tt    ]);
                al[mt][2] = __float_as_uint(Al[(r + g    ) * PADK + kk + tt + 4]);
                al[mt][3] = __float_as_uint(Al[(r + g + 8) * PADK + kk + tt + 4]);
            }
#pragma unroll
            for (int nt = 0; nt < 4; nt++) {
                int c = wn * 32 + nt * 8;
                bh[nt][0] = __float_as_uint(Bh[(c + g) * PADK + kk + tt    ]);
                bh[nt][1] = __float_as_uint(Bh[(c + g) * PADK + kk + tt + 4]);
                bl[nt][0] = __float_as_uint(Bl[(c + g) * PADK + kk + tt    ]);
                bl[nt][1] = __float_as_uint(Bl[(c + g) * PADK + kk + tt + 4]);
            }
#pragma unroll
            for (int mt = 0; mt < 4; mt++)
#pragma unroll
                for (int nt = 0; nt < 4; nt++) {
                    mma8(acc[mt][nt], ah[mt], bh[nt]);
                    mma8(acc[mt][nt], ah[mt], bl[nt]);
                    mma8(acc[mt][nt], al[mt], bh[nt]);
                }
        }
    }

    // ---- epilogue ----
#pragma unroll
    for (int mt = 0; mt < 4; mt++) {
        int r = m0 + wm * 64 + mt * 16;
#pragma unroll
        for (int nt = 0; nt < 4; nt++) {
            int c = n0 + wn * 32 + nt * 8 + 2 * tt;
            *(float2*)&outp[(size_t)(r + g    ) * D_ + c] = make_float2(acc[mt][nt][0], acc[mt][nt][1]);
            *(float2*)&outp[(size_t)(r + g + 8) * D_ + c] = make_float2(acc[mt][nt][2], acc[mt][nt][3]);
        }
    }
}

// ---------------- setup: sigma init + queries (warp-coop dots) ----------------
__global__ __launch_bounds__(256) void k_setup(const float* __restrict__ smu,
                                               const float* __restrict__ sls,
                                               const float* __restrict__ ni,
                                               const float* __restrict__ Wq) {
    int bk = blockIdx.x;
    int b = bk >> 3, k = bk & 7;
    int tid = threadIdx.x, wid = tid >> 5, lane = tid & 31;
    __shared__ float ss[D_];
    float sg   = expf(sls[k * D_ + tid]);
    float slot = smu[k * D_ + tid] + sg * ni[(b * K_ + k) * D_ + tid];
    ss[tid] = slot;
    g_sig[(b * K_ + k) * D_ + tid] = sg;
    __syncthreads();
    for (int j = 0; j < 32; j++) {
        int d = wid * 32 + j;
        const float* wr = Wq + (size_t)d * D_;
        float s = 0.f;
#pragma unroll
        for (int c = 0; c < 8; c++) s = fmaf(wr[lane + 32 * c], ss[lane + 32 * c], s);
#pragma unroll
        for (int o = 16; o; o >>= 1) s += __shfl_xor_sync(0xffffffffu, s, o);
        if (lane == 0) g_q[(b * K_ + k) * D_ + d] = s;
    }
}

// ---------------- gll with prep inlined ----------------
__global__ __launch_bounds__(256) void k_gll() {
    const int b  = blockIdx.y;
    const int n0 = blockIdx.x * 64;
    const int tid = threadIdx.x;
    const int wid = tid >> 5, lane = tid & 31;
    __shared__ float su[K_][D_];
    __shared__ float swm[K_][D_];
    __shared__ float sc1[K_];
    __shared__ float wsum[K_][8];
    float loc[K_];
#pragma unroll
    for (int i = 0; i < K_; i++) {
        int idx = (b * K_ + i) * D_ + tid;
        float sg = g_sig[idx];
        float q  = g_q[idx];
        float w  = 1.0f / fmaf(sg, sg, 1e-8f);
        su[i][tid]  = q * w;
        swm[i][tid] = -0.5f * w;
        loc[i] = logf(fabsf(sg) + 1e-8f) + q * q * w;
    }
#pragma unroll
    for (int i = 0; i < K_; i++) {
        float v = loc[i];
#pragma unroll
        for (int o = 16; o; o >>= 1) v += __shfl_xor_sync(0xffffffffu, v, o);
        if (lane == 0) wsum[i][wid] = v;
    }
    __syncthreads();
    if (tid < K_) {
        float s = 0.f;
#pragma unroll
        for (int j = 0; j < 8; j++) s += wsum[tid][j];
        sc1[tid] = LOGCONST - 0.5f * s;
    }
    __syncthreads();

    for (int r = 0; r < 8; r++) {
        int n = n0 + wid * 8 + r;
        const float* kr = g_keys + ((size_t)(b * N_ + n)) * D_;
        float acc[K_];
#pragma unroll
        for (int k = 0; k < K_; k++) acc[k] = 0.f;
#pragma unroll
        for (int j = 0; j < 8; j++) {
            int   dd = lane + 32 * j;
            float kv = kr[dd];
            float k2 = kv * kv;
#pragma unroll
            for (int k = 0; k < K_; k++) {
                acc[k] = fmaf(kv, su[k][dd], acc[k]);
                acc[k] = fmaf(k2, swm[k][dd], acc[k]);
            }
        }
#pragma unroll
        for (int o = 16; o; o >>= 1)
#pragma unroll
            for (int k = 0; k < K_; k++) acc[k] += __shfl_xor_sync(0xffffffffu, acc[k], o);
        if (lane == 0) {
#pragma unroll
            for (int k = 0; k < K_; k++) {
                float g = sc1[k] + acc[k];
                g = fminf(fmaxf(g, -10000.f), 10000.f);
                g_gll[((size_t)(b * N_ + n)) * K_ + k] = g;
            }
        }
    }
}

// ---------------- softmax reduce over N per (b,k) ----------------
__global__ void k_softmax() {
    int bk = blockIdx.x;
    int b = bk >> 3, k = bk & 7;
    int tid = threadIdx.x;
    __shared__ float red[256];
    float v[16];
    float mx = -3.4e38f;
#pragma unroll
    for (int i = 0; i < 16; i++) {
        int n = tid + (i << 8);
        v[i] = g_gll[((size_t)(b * N_ + n)) * K_ + k];
        mx = fmaxf(mx, v[i]);
    }
    red[tid] = mx; __syncthreads();
    for (int o = 128; o; o >>= 1) { if (tid < o) red[tid] = fmaxf(red[tid], red[tid + o]); __syncthreads(); }
    mx = red[0]; __syncthreads();
    float s = 0.f;
#pragma unroll
    for (int i = 0; i < 16; i++) s += expf(v[i] - mx);
    red[tid] = s; __syncthreads();
    for (int o = 128; o; o >>= 1) { if (tid < o) red[tid] += red[tid + o]; __syncthreads(); }
    if (tid == 0) { g_mx[bk] = mx; g_di[bk] = 1.0f / red[0]; }
}

// ---------------- attn + partial mu; transposed attn out on last iter --------
__global__ __launch_bounds__(256) void k_mu(float* __restrict__ outA, int last) {
    int ch = blockIdx.x, b = blockIdx.y;
    int n0 = ch * NC_;
    int tid = threadIdx.x;
    __shared__ __align__(16) float sa[NC_][K_];
    __shared__ float sm[K_], sd[K_];
    if (tid < K_) { sm[tid] = g_mx[b * K_ + tid]; sd[tid] = g_di[b * K_ + tid]; }
    __syncthreads();
#pragma unroll
    for (int i = 0; i < 4; i++) {
        int idx = tid + i * 256;
        int nl = idx >> 3, k = idx & 7;
        float g = g_gll[((size_t)(b * N_ + n0 + nl)) * K_ + k];
        float a = expf(g - sm[k]) * sd[k];
        sa[nl][k] = a;
        g_attn[((size_t)(b * N_ + n0 + nl)) * K_ + k] = a;
    }
    __syncthreads();
    if (last && tid < NC_) {
#pragma unroll
        for (int k = 0; k < K_; k++)
            outA[((size_t)(b * K_ + k)) * N_ + n0 + tid] = sa[tid][k];
    }
    int d = tid;
    float acc[K_];
#pragma unroll
    for (int k = 0; k < K_; k++) acc[k] = 0.f;
    const float* vb = g_vals + ((size_t)(b * N_ + n0)) * D_ + d;
    for (int nl = 0; nl < NC_; nl++) {
        float vv = vb[(size_t)nl * D_];
        float4 a0 = *(const float4*)&sa[nl][0];
        float4 a1 = *(const float4*)&sa[nl][4];
        acc[0] = fmaf(a0.x, vv, acc[0]); acc[1] = fmaf(a0.y, vv, acc[1]);
        acc[2] = fmaf(a0.z, vv, acc[2]); acc[3] = fmaf(a0.w, vv, acc[3]);
        acc[4] = fmaf(a1.x, vv, acc[4]); acc[5] = fmaf(a1.y, vv, acc[5]);
        acc[6] = fmaf(a1.z, vv, acc[6]); acc[7] = fmaf(a1.w, vv, acc[7]);
    }
#pragma unroll
    for (int k = 0; k < K_; k++)
        g_part[(((size_t)(b * CH_ + ch)) * K_ + k) * D_ + d] = acc[k];
}

// ---------------- reduce partials -> g_mu (0) or g_sig (1) ----------------
__global__ void k_redpart(int flag) {
    int k = blockIdx.x, b = blockIdx.y, d = threadIdx.x;
    float s = 0.f;
#pragma unroll 8
    for (int c = 0; c < CH_; c++)
        s += g_part[(((size_t)(b * CH_ + c)) * K_ + k) * D_ + d];
    if (flag) g_sig[(b * K_ + k) * D_ + d] = s;
    else      g_mu [(b * K_ + k) * D_ + d] = s;
}

// ---------------- partial sigma: sum attn*(v-mu)^2 ----------------
__global__ __launch_bounds__(256) void k_sigpass() {
    int ch = blockIdx.x, b = blockIdx.y;
    int n0 = ch * NC_;
    int tid = threadIdx.x;
    __shared__ __align__(16) float sa[NC_][K_];
#pragma unroll
    for (int i = 0; i < 4; i++) {
        int idx = tid + i * 256;
        int nl = idx >> 3, k = idx & 7;
        sa[nl][k] = g_attn[((size_t)(b * N_ + n0 + nl)) * K_ + k];
    }
    int d = tid;
    float mu8[K_];
#pragma unroll
    for (int k = 0; k < K_; k++) mu8[k] = g_mu[(b * K_ + k) * D_ + d];
    __syncthreads();
    float acc[K_];
#pragma unroll
    for (int k = 0; k < K_; k++) acc[k] = 0.f;
    const float* vb = g_vals + ((size_t)(b * N_ + n0)) * D_ + d;
    for (int nl = 0; nl < NC_; nl++) {
        float vv = vb[(size_t)nl * D_];
        float4 a0 = *(const float4*)&sa[nl][0];
        float4 a1 = *(const float4*)&sa[nl][4];
        float t;
        t = vv - mu8[0]; acc[0] = fmaf(a0.x, t * t, acc[0]);
        t = vv - mu8[1]; acc[1] = fmaf(a0.y, t * t, acc[1]);
        t = vv - mu8[2]; acc[2] = fmaf(a0.z, t * t, acc[2]);
        t = vv - mu8[3]; acc[3] = fmaf(a0.w, t * t, acc[3]);
        t = vv - mu8[4]; acc[4] = fmaf(a1.x, t * t, acc[4]);
        t = vv - mu8[5]; acc[5] = fmaf(a1.y, t * t, acc[5]);
        t = vv - mu8[6]; acc[6] = fmaf(a1.z, t * t, acc[6]);
        t = vv - mu8[7]; acc[7] = fmaf(a1.w, t * t, acc[7]);
    }
#pragma unroll
    for (int k = 0; k < K_; k++)
        g_part[(((size_t)(b * CH_ + ch)) * K_ + k) * D_ + d] = acc[k];
}

// ---------------- final ----------------
__global__ void k_final(const float* __restrict__ nf, float* __restrict__ out) {
    int k = blockIdx.x, b = blockIdx.y, d = threadIdx.x;
    int idx = (b * K_ + k) * D_ + d;
    out[idx] = g_mu[idx] + fmaxf(fabsf(g_sig[idx]), 1e-8f) * nf[idx];
}

// ---------------------------------------------------------------------------
extern "C" void kernel_launch(void* const* d_in, const int* in_sizes, int n_in,
                              void* d_out, int out_size) {
    const float* emb  = (const float*)d_in[0];
    const float* smu  = (const float*)d_in[1];
    const float* sls  = (const float*)d_in[2];
    const float* Wq   = (const float*)d_in[4];
    const float* Wk   = (const float*)d_in[5];
    const float* Wv   = (const float*)d_in[6];
    const float* lnsc = (const float*)d_in[7];
    const float* lnb  = (const float*)d_in[8];
    const float* ni   = (const float*)d_in[9];
    const float* nf   = (const float*)d_in[10];
    float* out      = (float*)d_out;
    float* out_attn = out + B_ * K_ * D_;

    static int smem_set = 0;
    if (!smem_set) {
        cudaFuncSetAttribute(k_gemm_mma, cudaFuncAttributeMaxDynamicSharedMemorySize, GEMM_SMEM);
        smem_set = 1;
    }

    k_lnstats<<<N_ * B_ / 8, 256>>>(emb);
    k_gemm_mma<<<dim3(256, 4), 256, GEMM_SMEM>>>(emb, lnsc, lnb, Wk, Wv);
    k_setup<<<B_ * K_, 256>>>(smu, sls, ni, Wq);

    for (int it = 0; it < 3; it++) {
        int last = (it == 2) ? 1 : 0;
        k_gll<<<dim3(N_ / 64, B_), 256>>>();
        k_softmax<<<B_ * K_, 256>>>();
        k_mu<<<dim3(CH_, B_), 256>>>(out_attn, last);
        k_redpart<<<dim3(K_, B_), 256>>>(0);
        k_sigpass<<<dim3(CH_, B_), 256>>>();
        k_redpart<<<dim3(K_, B_), 256>>>(1);
    }
    k_final<<<dim3(K_, B_), 256>>>(nf, out);
}

// round 10
// speedup vs baseline: 1.4622x; 1.0991x over previous
#include <cuda_runtime.h>
#include <math.h>

typedef unsigned int u32;

#define B_  8
#define N_  4096
#define K_  8
#define D_  256
#define NCH 64
#define CR  64
#define LOGCONST (-235.24826450320013f)

// ---------------- scratch ----------------
__device__ float2 g_lnst[B_ * N_];
__device__ float  g_keys[B_ * N_ * D_];
__device__ float  g_vals[B_ * N_ * D_];
__device__ float  g_gll [B_ * N_ * K_];
__device__ float  g_attn[B_ * N_ * K_];
__device__ float  g_q   [B_ * K_ * D_];
__device__ float  g_sig [B_ * K_ * D_];
__device__ float  g_mu  [B_ * K_ * D_];
__device__ float  g_mx  [B_ * K_];
__device__ float  g_di  [B_ * K_];
__device__ float  g_part[B_ * NCH * K_ * D_];

// ---------------- LayerNorm row stats ----------------
__global__ void k_lnstats(const float* __restrict__ emb) {
    int warp = threadIdx.x >> 5, lane = threadIdx.x & 31;
    int row  = blockIdx.x * 8 + warp;
    const float* base = emb + (size_t)row * D_;
    float s = 0.f, sq = 0.f;
#pragma unroll
    for (int j = 0; j < 8; j++) {
        float v = base[lane + 32 * j];
        s += v;
        sq = fmaf(v, v, sq);
    }
#pragma unroll
    for (int o = 16; o; o >>= 1) {
        s  += __shfl_xor_sync(0xffffffffu, s,  o);
        sq += __shfl_xor_sync(0xffffffffu, sq, o);
    }
    if (lane == 0) {
        float mean = s * (1.0f / D_);
        float var  = sq * (1.0f / D_) - mean * mean;
        g_lnst[row] = make_float2(mean, 1.0f / sqrtf(var + 1e-5f));
    }
}

// ============ tf32x3 GEMM via mma.sync (unchanged from passing R7) ============
__device__ __forceinline__ void mma8(float* c, const u32* a, const u32* b) {
    asm volatile(
        "mma.sync.aligned.m16n8k8.row.col.f32.tf32.tf32.f32 "
        "{%0,%1,%2,%3}, {%4,%5,%6,%7}, {%8,%9}, {%0,%1,%2,%3};"
        : "+f"(c[0]), "+f"(c[1]), "+f"(c[2]), "+f"(c[3])
        : "r"(a[0]), "r"(a[1]), "r"(a[2]), "r"(a[3]), "r"(b[0]), "r"(b[1]));
}
__device__ __forceinline__ u32 to_tf32(float x) {
    u32 r;
    asm("cvt.rna.tf32.f32 %0, %1;" : "=r"(r) : "f"(x));
    return r;
}

#define PADK 36
#define SMA (128 * PADK)
#define GEMM_SMEM (4 * SMA * 4)

__global__ __launch_bounds__(256) void k_gemm_mma(const float* __restrict__ emb,
                                                  const float* __restrict__ lnsc,
                                                  const float* __restrict__ lnb,
                                                  const float* __restrict__ Wk,
                                                  const float* __restrict__ Wv) {
    extern __shared__ float sh[];
    float* Ah = sh;
    float* Al = sh + SMA;
    float* Bh = sh + 2 * SMA;
    float* Bl = sh + 3 * SMA;
    const int tid = threadIdx.x, lane = tid & 31, wid = tid >> 5;
    const int m0 = blockIdx.x * 128;
    const int nq = blockIdx.y;
    const float* Bsrc = (nq < 2) ? Wk : Wv;
    float* outp = (nq < 2) ? g_keys : g_vals;
    const int n0 = (nq & 1) * 128;
    const int wm = wid >> 2, wn = wid & 3;
    const int g = lane >> 2, tt = lane & 3;

    float acc[4][4][4];
#pragma unroll
    for (int i = 0; i < 4; i++)
#pragma unroll
        for (int j = 0; j < 4; j++)
#pragma unroll
            for (int r = 0; r < 4; r++) acc[i][j][r] = 0.f;

    for (int kc = 0; kc < 8; kc++) {
        const int k0 = kc * 32;
        if (kc) __syncthreads();
#pragma unroll
        for (int i = 0; i < 4; i++) {
            int lin = tid + i * 256;
            int row = lin >> 3, sg = (lin & 7) * 4;
            float2 st = g_lnst[m0 + row];
            float4 a  = *(const float4*)&emb[(size_t)(m0 + row) * D_ + k0 + sg];
            float4 sc = *(const float4*)&lnsc[k0 + sg];
            float4 bi = *(const float4*)&lnb[k0 + sg];
            float x[4];
            x[0] = fmaf((a.x - st.x) * st.y, sc.x, bi.x);
            x[1] = fmaf((a.y - st.x) * st.y, sc.y, bi.y);
            x[2] = fmaf((a.z - st.x) * st.y, sc.z, bi.z);
            x[3] = fmaf((a.w - st.x) * st.y, sc.w, bi.w);
            u32 hb[4], lb[4];
#pragma unroll
            for (int j = 0; j < 4; j++) {
                hb[j] = __float_as_uint(x[j]) & 0xffffe000u;
                lb[j] = to_tf32(x[j] - __uint_as_float(hb[j]));
            }
            *(float4*)&Ah[row * PADK + sg] =
                make_float4(__uint_as_float(hb[0]), __uint_as_float(hb[1]),
                            __uint_as_float(hb[2]), __uint_as_float(hb[3]));
            *(float4*)&Al[row * PADK + sg] =
                make_float4(__uint_as_float(lb[0]), __uint_as_float(lb[1]),
                            __uint_as_float(lb[2]), __uint_as_float(lb[3]));
        }
#pragma unroll
        for (int i = 0; i < 4; i++) {
            int lin = tid + i * 256;
            int row = lin >> 3, sg = (lin & 7) * 4;
            float4 a = *(const float4*)&Bsrc[(size_t)(n0 + row) * D_ + k0 + sg];
            float x[4] = {a.x, a.y, a.z, a.w};
            u32 hb[4], lb[4];
#pragma unroll
            for (int j = 0; j < 4; j++) {
                hb[j] = __float_as_uint(x[j]) & 0xffffe000u;
                lb[j] = to_tf32(x[j] - __uint_as_float(hb[j]));
            }
            *(float4*)&Bh[row * PADK + sg] =
                make_float4(__uint_as_float(hb[0]), __uint_as_float(hb[1]),
                            __uint_as_float(hb[2]), __uint_as_float(hb[3]));
            *(float4*)&Bl[row * PADK + sg] =
                make_float4(__uint_as_float(lb[0]), __uint_as_float(lb[1]),
                            __uint_as_float(lb[2]), __uint_as_float(lb[3]));
        }
        __syncthreads();

#pragma unroll
        for (int ks = 0; ks < 4; ks++) {
            const int kk = ks * 8;
            u32 ah[4][4], al[4][4], bh[4][2], bl[4][2];
#pragma unroll
            for (int mt = 0; mt < 4; mt++) {
                int r = wm * 64 + mt * 16;
                ah[mt][0] = __float_as_uint(Ah[(r + g    ) * PADK + kk + tt    ]);
                ah[mt][1] = __float_as_uint(Ah[(r + g + 8) * PADK + kk + tt    ]);
                ah[mt][2] = __float_as_uint(Ah[(r + g    ) * PADK + kk + tt + 4]);
                ah[mt][3] = __float_as_uint(Ah[(r + g + 8) * PADK + kk + tt + 4]);
                al[mt][0] = __float_as_uint(Al[(r + g    ) * PADK + kk + tt    ]);
                al[mt][1] = __float_as_uint(Al[(r + g + 8) * PADK + kk + tt    ]);
                al[mt][2] = __float_as_uint(Al[(r + g    ) * PADK + kk + tt + 4]);
                al[mt][3] = __float_as_uint(Al[(r + g + 8) * PADK + kk + tt + 4]);
            }
#pragma unroll
            for (int nt = 0; nt < 4; nt++) {
                int c = wn * 32 + nt * 8;
                bh[nt][0] = __float_as_uint(Bh[(c + g) * PADK + kk + tt    ]);
                bh[nt][1] = __float_as_uint(Bh[(c + g) * PADK + kk + tt + 4]);
                bl[nt][0] = __float_as_uint(Bl[(c + g) * PADK + kk + tt    ]);
                bl[nt][1] = __float_as_uint(Bl[(c + g) * PADK + kk + tt + 4]);
            }
#pragma unroll
            for (int mt = 0; mt < 4; mt++)
#pragma unroll
                for (int nt = 0; nt < 4; nt++) {
                    mma8(acc[mt][nt], ah[mt], bh[nt]);
                    mma8(acc[mt][nt], ah[mt], bl[nt]);
                    mma8(acc[mt][nt], al[mt], bh[nt]);
                }
        }
    }

#pragma unroll
    for (int mt = 0; mt < 4; mt++) {
        int r = m0 + wm * 64 + mt * 16;
#pragma unroll
        for (int nt = 0; nt < 4; nt++) {
            int c = n0 + wn * 32 + nt * 8 + 2 * tt;
            *(float2*)&outp[(size_t)(r + g    ) * D_ + c] = make_float2(acc[mt][nt][0], acc[mt][nt][1]);
            *(float2*)&outp[(size_t)(r + g + 8) * D_ + c] = make_float2(acc[mt][nt][2], acc[mt][nt][3]);
        }
    }
}

// ---------------- setup: sigma init + queries ----------------
__global__ __launch_bounds__(256) void k_setup(const float* __restrict__ smu,
                                               const float* __restrict__ sls,
                                               const float* __restrict__ ni,
                                               const float* __restrict__ Wq) {
    int bk = blockIdx.x;
    int b = bk >> 3, k = bk & 7;
    int tid = threadIdx.x, wid = tid >> 5, lane = tid & 31;
    __shared__ float ss[D_];
    float sg   = expf(sls[k * D_ + tid]);
    float slot = smu[k * D_ + tid] + sg * ni[(b * K_ + k) * D_ + tid];
    ss[tid] = slot;
    g_sig[(b * K_ + k) * D_ + tid] = sg;
    __syncthreads();
    for (int j = 0; j < 32; j++) {
        int d = wid * 32 + j;
        const float* wr = Wq + (size_t)d * D_;
        float s = 0.f;
#pragma unroll
        for (int c = 0; c < 8; c++) s = fmaf(wr[lane + 32 * c], ss[lane + 32 * c], s);
#pragma unroll
        for (int o = 16; o; o >>= 1) s += __shfl_xor_sync(0xffffffffu, s, o);
        if (lane == 0) g_q[(b * K_ + k) * D_ + d] = s;
    }
}

// ---------------- gll: 4 rows per warp, smem traffic /4 ----------------
__global__ __launch_bounds__(256) void k_gll() {
    const int b  = blockIdx.y;
    const int n0 = blockIdx.x * 32;
    const int tid = threadIdx.x;
    const int wid = tid >> 5, lane = tid & 31;
    __shared__ float su[K_][D_];
    __shared__ float swm[K_][D_];
    __shared__ float sc1[K_];
    __shared__ float wsum[K_][8];
    float loc[K_];
#pragma unroll
    for (int i = 0; i < K_; i++) {
        int idx = (b * K_ + i) * D_ + tid;
        float sg = g_sig[idx];
        float q  = g_q[idx];
        float w  = 1.0f / fmaf(sg, sg, 1e-8f);
        su[i][tid]  = q * w;
        swm[i][tid] = -0.5f * w;
        loc[i] = logf(fabsf(sg) + 1e-8f) + q * q * w;
    }
#pragma unroll
    for (int i = 0; i < K_; i++) {
        float v = loc[i];
#pragma unroll
        for (int o = 16; o; o >>= 1) v += __shfl_xor_sync(0xffffffffu, v, o);
        if (lane == 0) wsum[i][wid] = v;
    }
    __syncthreads();
    if (tid < K_) {
        float s = 0.f;
#pragma unroll
        for (int j = 0; j < 8; j++) s += wsum[tid][j];
        sc1[tid] = LOGCONST - 0.5f * s;
    }
    __syncthreads();

    const float* kr = g_keys + ((size_t)(b * N_ + n0 + wid * 4)) * D_;
    float acc[4][K_];
#pragma unroll
    for (int r = 0; r < 4; r++)
#pragma unroll
        for (int k = 0; k < K_; k++) acc[r][k] = 0.f;

#pragma unroll
    for (int j = 0; j < 8; j++) {
        int dd = lane + 32 * j;
        float v0 = kr[dd];
        float v1 = kr[D_ + dd];
        float v2 = kr[2 * D_ + dd];
        float v3 = kr[3 * D_ + dd];
        float q0 = v0 * v0, q1 = v1 * v1, q2 = v2 * v2, q3 = v3 * v3;
#pragma unroll
        for (int k = 0; k < K_; k++) {
            float s = su[k][dd], w = swm[k][dd];
            acc[0][k] = fmaf(v0, s, fmaf(q0, w, acc[0][k]));
            acc[1][k] = fmaf(v1, s, fmaf(q1, w, acc[1][k]));
            acc[2][k] = fmaf(v2, s, fmaf(q2, w, acc[2][k]));
            acc[3][k] = fmaf(v3, s, fmaf(q3, w, acc[3][k]));
        }
    }
#pragma unroll
    for (int r = 0; r < 4; r++) {
#pragma unroll
        for (int o = 16; o; o >>= 1)
#pragma unroll
            for (int k = 0; k < K_; k++) acc[r][k] += __shfl_xor_sync(0xffffffffu, acc[r][k], o);
        if (lane == 0) {
            int n = n0 + wid * 4 + r;
#pragma unroll
            for (int k = 0; k < K_; k++) {
                float g = sc1[k] + acc[r][k];
                g = fminf(fmaxf(g, -10000.f), 10000.f);
                g_gll[((size_t)(b * N_ + n)) * K_ + k] = g;
            }
        }
    }
}

// ---------------- softmax reduce over N per (b,k) ----------------
__global__ void k_softmax() {
    int bk = blockIdx.x;
    int b = bk >> 3, k = bk & 7;
    int tid = threadIdx.x;
    __shared__ float red[256];
    float v[16];
    float mx = -3.4e38f;
#pragma unroll
    for (int i = 0; i < 16; i++) {
        int n = tid + (i << 8);
        v[i] = g_gll[((size_t)(b * N_ + n)) * K_ + k];
        mx = fmaxf(mx, v[i]);
    }
    red[tid] = mx; __syncthreads();
    for (int o = 128; o; o >>= 1) { if (tid < o) red[tid] = fmaxf(red[tid], red[tid + o]); __syncthreads(); }
    mx = red[0]; __syncthreads();
    float s = 0.f;
#pragma unroll
    for (int i = 0; i < 16; i++) s += expf(v[i] - mx);
    red[tid] = s; __syncthreads();
    for (int o = 128; o; o >>= 1) { if (tid < o) red[tid] += red[tid + o]; __syncthreads(); }
    if (tid == 0) { g_mx[bk] = mx; g_di[bk] = 1.0f / red[0]; }
}

// ---------------- attn + partial mu (64-row chunks) ----------------
__global__ __launch_bounds__(256) void k_mu(float* __restrict__ outA, int last) {
    int ch = blockIdx.x, b = blockIdx.y;
    int n0 = ch * CR;
    int tid = threadIdx.x;
    __shared__ __align__(16) float sa[CR][K_];
    __shared__ float sm[K_], sd[K_];
    if (tid < K_) { sm[tid] = g_mx[b * K_ + tid]; sd[tid] = g_di[b * K_ + tid]; }
    __syncthreads();
#pragma unroll
    for (int i = 0; i < 2; i++) {
        int idx = tid + i * 256;
        int nl = idx >> 3, k = idx & 7;
        float g = g_gll[((size_t)(b * N_ + n0 + nl)) * K_ + k];
        float a = expf(g - sm[k]) * sd[k];
        sa[nl][k] = a;
        g_attn[((size_t)(b * N_ + n0 + nl)) * K_ + k] = a;
    }
    __syncthreads();
    if (last && tid < CR) {
#pragma unroll
        for (int k = 0; k < K_; k++)
            outA[((size_t)(b * K_ + k)) * N_ + n0 + tid] = sa[tid][k];
    }
    int d = tid;
    float acc[K_];
#pragma unroll
    for (int k = 0; k < K_; k++) acc[k] = 0.f;
    const float* vb = g_vals + ((size_t)(b * N_ + n0)) * D_ + d;
#pragma unroll 4
    for (int nl = 0; nl < CR; nl++) {
        float vv = vb[(size_t)nl * D_];
        float4 a0 = *(const float4*)&sa[nl][0];
        float4 a1 = *(const float4*)&sa[nl][4];
        acc[0] = fmaf(a0.x, vv, acc[0]); acc[1] = fmaf(a0.y, vv, acc[1]);
        acc[2] = fmaf(a0.z, vv, acc[2]); acc[3] = fmaf(a0.w, vv, acc[3]);
        acc[4] = fmaf(a1.x, vv, acc[4]); acc[5] = fmaf(a1.y, vv, acc[5]);
        acc[6] = fmaf(a1.z, vv, acc[6]); acc[7] = fmaf(a1.w, vv, acc[7]);
    }
#pragma unroll
    for (int k = 0; k < K_; k++)
        g_part[(((size_t)(b * NCH + ch)) * K_ + k) * D_ + d] = acc[k];
}

// ---------------- reduce partials -> g_mu (0) or g_sig (1) ----------------
__global__ void k_redpart(int flag) {
    int k = blockIdx.x, b = blockIdx.y, d = threadIdx.x;
    float s = 0.f;
#pragma unroll 8
    for (int c = 0; c < NCH; c++)
        s += g_part[(((size_t)(b * NCH + c)) * K_ + k) * D_ + d];
    if (flag) g_sig[(b * K_ + k) * D_ + d] = s;
    else      g_mu [(b * K_ + k) * D_ + d] = s;
}

// ---------------- partial sigma (64-row chunks) ----------------
__global__ __launch_bounds__(256) void k_sigpass() {
    int ch = blockIdx.x, b = blockIdx.y;
    int n0 = ch * CR;
    int tid = threadIdx.x;
    __shared__ __align__(16) float sa[CR][K_];
#pragma unroll
    for (int i = 0; i < 2; i++) {
        int idx = tid + i * 256;
        int nl = idx >> 3, k = idx & 7;
        sa[nl][k] = g_attn[((size_t)(b * N_ + n0 + nl)) * K_ + k];
    }
    int d = tid;
    float mu8[K_];
#pragma unroll
    for (int k = 0; k < K_; k++) mu8[k] = g_mu[(b * K_ + k) * D_ + d];
    __syncthreads();
    float acc[K_];
#pragma unroll
    for (int k = 0; k < K_; k++) acc[k] = 0.f;
    const float* vb = g_vals + ((size_t)(b * N_ + n0)) * D_ + d;
#pragma unroll 4
    for (int nl = 0; nl < CR; nl++) {
        float vv = vb[(size_t)nl * D_];
        float4 a0 = *(const float4*)&sa[nl][0];
        float4 a1 = *(const float4*)&sa[nl][4];
        float t;
        t = vv - mu8[0]; acc[0] = fmaf(a0.x, t * t, acc[0]);
        t = vv - mu8[1]; acc[1] = fmaf(a0.y, t * t, acc[1]);
        t = vv - mu8[2]; acc[2] = fmaf(a0.z, t * t, acc[2]);
        t = vv - mu8[3]; acc[3] = fmaf(a0.w, t * t, acc[3]);
        t = vv - mu8[4]; acc[4] = fmaf(a1.x, t * t, acc[4]);
        t = vv - mu8[5]; acc[5] = fmaf(a1.y, t * t, acc[5]);
        t = vv - mu8[6]; acc[6] = fmaf(a1.z, t * t, acc[6]);
        t = vv - mu8[7]; acc[7] = fmaf(a1.w, t * t, acc[7]);
    }
#pragma unroll
    for (int k = 0; k < K_; k++)
        g_part[(((size_t)(b * NCH + ch)) * K_ + k) * D_ + d] = acc[k];
}

// ---------------- final ----------------
__global__ void k_final(const float* __restrict__ nf, float* __restrict__ out) {
    int k = blockIdx.x, b = blockIdx.y, d = threadIdx.x;
    int idx = (b * K_ + k) * D_ + d;
    out[idx] = g_mu[idx] + fmaxf(fabsf(g_sig[idx]), 1e-8f) * nf[idx];
}

// ---------------------------------------------------------------------------
extern "C" void kernel_launch(void* const* d_in, const int* in_sizes, int n_in,
                              void* d_out, int out_size) {
    const float* emb  = (const float*)d_in[0];
    const float* smu  = (const float*)d_in[1];
    const float* sls  = (const float*)d_in[2];
    const float* Wq   = (const float*)d_in[4];
    const float* Wk   = (const float*)d_in[5];
    const float* Wv   = (const float*)d_in[6];
    const float* lnsc = (const float*)d_in[7];
    const float* lnb  = (const float*)d_in[8];
    const float* ni   = (const float*)d_in[9];
    const float* nf   = (const float*)d_in[10];
    float* out      = (float*)d_out;
    float* out_attn = out + B_ * K_ * D_;

    static int smem_set = 0;
    if (!smem_set) {
        cudaFuncSetAttribute(k_gemm_mma, cudaFuncAttributeMaxDynamicSharedMemorySize, GEMM_SMEM);
        smem_set = 1;
    }

    k_lnstats<<<N_ * B_ / 8, 256>>>(emb);
    k_gemm_mma<<<dim3(256, 4), 256, GEMM_SMEM>>>(emb, lnsc, lnb, Wk, Wv);
    k_setup<<<B_ * K_, 256>>>(smu, sls, ni, Wq);

    for (int it = 0; it < 3; it++) {
        int last = (it == 2) ? 1 : 0;
        k_gll<<<dim3(N_ / 32, B_), 256>>>();
        k_softmax<<<B_ * K_, 256>>>();
        k_mu<<<dim3(NCH, B_), 256>>>(out_attn, last);
        k_redpart<<<dim3(K_, B_), 256>>>(0);
        k_sigpass<<<dim3(NCH, B_), 256>>>();
        k_redpart<<<dim3(K_, B_), 256>>>(1);
    }
    k_final<<<dim3(K_, B_), 256>>>(nf, out);
}

// round 11
// speedup vs baseline: 1.6491x; 1.1279x over previous
#include <cuda_runtime.h>
#include <math.h>

typedef unsigned int u32;

#define B_  8
#define N_  4096
#define K_  8
#define D_  256
#define NCH 64
#define CR  64
#define LOGCONST (-235.24826450320013f)

// ---------------- scratch ----------------
__device__ float2 g_lnst[B_ * N_];
__device__ float  g_keys[B_ * N_ * D_];
__device__ float  g_vals[B_ * N_ * D_];
__device__ float  g_gll [B_ * N_ * K_];
__device__ float  g_q   [B_ * K_ * D_];
__device__ float  g_sig [B_ * K_ * D_];
__device__ float  g_mu  [B_ * K_ * D_];
__device__ float  g_mx  [B_ * K_];
__device__ float  g_di  [B_ * K_];
__device__ float  g_p1  [B_ * NCH * K_ * D_];
__device__ float  g_p2  [B_ * NCH * K_ * D_];

// ---------------- LayerNorm row stats ----------------
__global__ void k_lnstats(const float* __restrict__ emb) {
    int warp = threadIdx.x >> 5, lane = threadIdx.x & 31;
    int row  = blockIdx.x * 8 + warp;
    const float* base = emb + (size_t)row * D_;
    float s = 0.f, sq = 0.f;
#pragma unroll
    for (int j = 0; j < 8; j++) {
        float v = base[lane + 32 * j];
        s += v;
        sq = fmaf(v, v, sq);
    }
#pragma unroll
    for (int o = 16; o; o >>= 1) {
        s  += __shfl_xor_sync(0xffffffffu, s,  o);
        sq += __shfl_xor_sync(0xffffffffu, sq, o);
    }
    if (lane == 0) {
        float mean = s * (1.0f / D_);
        float var  = sq * (1.0f / D_) - mean * mean;
        g_lnst[row] = make_float2(mean, 1.0f / sqrtf(var + 1e-5f));
    }
}

// ============ tf32x3 GEMM via mma.sync (unchanged — proven) ============
__device__ __forceinline__ void mma8(float* c, const u32* a, const u32* b) {
    asm volatile(
        "mma.sync.aligned.m16n8k8.row.col.f32.tf32.tf32.f32 "
        "{%0,%1,%2,%3}, {%4,%5,%6,%7}, {%8,%9}, {%0,%1,%2,%3};"
        : "+f"(c[0]), "+f"(c[1]), "+f"(c[2]), "+f"(c[3])
        : "r"(a[0]), "r"(a[1]), "r"(a[2]), "r"(a[3]), "r"(b[0]), "r"(b[1]));
}
__device__ __forceinline__ u32 to_tf32(float x) {
    u32 r;
    asm("cvt.rna.tf32.f32 %0, %1;" : "=r"(r) : "f"(x));
    return r;
}

#define PADK 36
#define SMA (128 * PADK)
#define GEMM_SMEM (4 * SMA * 4)

__global__ __launch_bounds__(256) void k_gemm_mma(const float* __restrict__ emb,
                                                  const float* __restrict__ lnsc,
                                                  const float* __restrict__ lnb,
                                                  const float* __restrict__ Wk,
                                                  const float* __restrict__ Wv) {
    extern __shared__ float sh[];
    float* Ah = sh;
    float* Al = sh + SMA;
    float* Bh = sh + 2 * SMA;
    float* Bl = sh + 3 * SMA;
    const int tid = threadIdx.x, lane = tid & 31, wid = tid >> 5;
    const int m0 = blockIdx.x * 128;
    const int nq = blockIdx.y;
    const float* Bsrc = (nq < 2) ? Wk : Wv;
    float* outp = (nq < 2) ? g_keys : g_vals;
    const int n0 = (nq & 1) * 128;
    const int wm = wid >> 2, wn = wid & 3;
    const int g = lane >> 2, tt = lane & 3;

    float acc[4][4][4];
#pragma unroll
    for (int i = 0; i < 4; i++)
#pragma unroll
        for (int j = 0; j < 4; j++)
#pragma unroll
            for (int r = 0; r < 4; r++) acc[i][j][r] = 0.f;

    for (int kc = 0; kc < 8; kc++) {
        const int k0 = kc * 32;
        if (kc) __syncthreads();
#pragma unroll
        for (int i = 0; i < 4; i++) {
            int lin = tid + i * 256;
            int row = lin >> 3, sg = (lin & 7) * 4;
            float2 st = g_lnst[m0 + row];
            float4 a  = *(const float4*)&emb[(size_t)(m0 + row) * D_ + k0 + sg];
            float4 sc = *(const float4*)&lnsc[k0 + sg];
            float4 bi = *(const float4*)&lnb[k0 + sg];
            float x[4];
            x[0] = fmaf((a.x - st.x) * st.y, sc.x, bi.x);
            x[1] = fmaf((a.y - st.x) * st.y, sc.y, bi.y);
            x[2] = fmaf((a.z - st.x) * st.y, sc.z, bi.z);
            x[3] = fmaf((a.w - st.x) * st.y, sc.w, bi.w);
            u32 hb[4], lb[4];
#pragma unroll
            for (int j = 0; j < 4; j++) {
                hb[j] = __float_as_uint(x[j]) & 0xffffe000u;
                lb[j] = to_tf32(x[j] - __uint_as_float(hb[j]));
            }
            *(float4*)&Ah[row * PADK + sg] =
                make_float4(__uint_as_float(hb[0]), __uint_as_float(hb[1]),
                            __uint_as_float(hb[2]), __uint_as_float(hb[3]));
            *(float4*)&Al[row * PADK + sg] =
                make_float4(__uint_as_float(lb[0]), __uint_as_float(lb[1]),
                            __uint_as_float(lb[2]), __uint_as_float(lb[3]));
        }
#pragma unroll
        for (int i = 0; i < 4; i++) {
            int lin = tid + i * 256;
            int row = lin >> 3, sg = (lin & 7) * 4;
            float4 a = *(const float4*)&Bsrc[(size_t)(n0 + row) * D_ + k0 + sg];
            float x[4] = {a.x, a.y, a.z, a.w};
            u32 hb[4], lb[4];
#pragma unroll
            for (int j = 0; j < 4; j++) {
                hb[j] = __float_as_uint(x[j]) & 0xffffe000u;
                lb[j] = to_tf32(x[j] - __uint_as_float(hb[j]));
            }
            *(float4*)&Bh[row * PADK + sg] =
                make_float4(__uint_as_float(hb[0]), __uint_as_float(hb[1]),
                            __uint_as_float(hb[2]), __uint_as_float(hb[3]));
            *(float4*)&Bl[row * PADK + sg] =
                make_float4(__uint_as_float(lb[0]), __uint_as_float(lb[1]),
                            __uint_as_float(lb[2]), __uint_as_float(lb[3]));
        }
        __syncthreads();

#pragma unroll
        for (int ks = 0; ks < 4; ks++) {
            const int kk = ks * 8;
            u32 ah[4][4], al[4][4], bh[4][2], bl[4][2];
#pragma unroll
            for (int mt = 0; mt < 4; mt++) {
                int r = wm * 64 + mt * 16;
                ah[mt][0] = __float_as_uint(Ah[(r + g    ) * PADK + kk + tt    ]);
                ah[mt][1] = __float_as_uint(Ah[(r + g + 8) * PADK + kk + tt    ]);
                ah[mt][2] = __float_as_uint(Ah[(r + g    ) * PADK + kk + tt + 4]);
                ah[mt][3] = __float_as_uint(Ah[(r + g + 8) * PADK + kk + tt + 4]);
                al[mt][0] = __float_as_uint(Al[(r + g    ) * PADK + kk + tt    ]);
                al[mt][1] = __float_as_uint(Al[(r + g + 8) * PADK + kk + tt    ]);
                al[mt][2] = __float_as_uint(Al[(r + g    ) * PADK + kk + tt + 4]);
                al[mt][3] = __float_as_uint(Al[(r + g + 8) * PADK + kk + tt + 4]);
            }
#pragma unroll
            for (int nt = 0; nt < 4; nt++) {
                int c = wn * 32 + nt * 8;
                bh[nt][0] = __float_as_uint(Bh[(c + g) * PADK + kk + tt    ]);
                bh[nt][1] = __float_as_uint(Bh[(c + g) * PADK + kk + tt + 4]);
                bl[nt][0] = __float_as_uint(Bl[(c + g) * PADK + kk + tt    ]);
                bl[nt][1] = __float_as_uint(Bl[(c + g) * PADK + kk + tt + 4]);
            }
#pragma unroll
            for (int mt = 0; mt < 4; mt++)
#pragma unroll
                for (int nt = 0; nt < 4; nt++) {
                    mma8(acc[mt][nt], ah[mt], bh[nt]);
                    mma8(acc[mt][nt], ah[mt], bl[nt]);
                    mma8(acc[mt][nt], al[mt], bh[nt]);
                }
        }
    }

#pragma unroll
    for (int mt = 0; mt < 4; mt++) {
        int r = m0 + wm * 64 + mt * 16;
#pragma unroll
        for (int nt = 0; nt < 4; nt++) {
            int c = n0 + wn * 32 + nt * 8 + 2 * tt;
            *(float2*)&outp[(size_t)(r + g    ) * D_ + c] = make_float2(acc[mt][nt][0], acc[mt][nt][1]);
            *(float2*)&outp[(size_t)(r + g + 8) * D_ + c] = make_float2(acc[mt][nt][2], acc[mt][nt][3]);
        }
    }
}

// ---------------- setup: sigma init + queries ----------------
__global__ __launch_bounds__(256) void k_setup(const float* __restrict__ smu,
                                               const float* __restrict__ sls,
                                               const float* __restrict__ ni,
                                               const float* __restrict__ Wq) {
    int bk = blockIdx.x;
    int b = bk >> 3, k = bk & 7;
    int tid = threadIdx.x, wid = tid >> 5, lane = tid & 31;
    __shared__ float ss[D_];
    float sg   = expf(sls[k * D_ + tid]);
    float slot = smu[k * D_ + tid] + sg * ni[(b * K_ + k) * D_ + tid];
    ss[tid] = slot;
    g_sig[(b * K_ + k) * D_ + tid] = sg;
    __syncthreads();
    for (int j = 0; j < 32; j++) {
        int d = wid * 32 + j;
        const float* wr = Wq + (size_t)d * D_;
        float s = 0.f;
#pragma unroll
        for (int c = 0; c < 8; c++) s = fmaf(wr[lane + 32 * c], ss[lane + 32 * c], s);
#pragma unroll
        for (int o = 16; o; o >>= 1) s += __shfl_xor_sync(0xffffffffu, s, o);
        if (lane == 0) g_q[(b * K_ + k) * D_ + d] = s;
    }
}

// ---------------- gll: 4 rows/warp, float2-interleaved (u, -w/2) ----------------
__global__ __launch_bounds__(256) void k_gll() {
    const int b  = blockIdx.y;
    const int n0 = blockIdx.x * 32;
    const int tid = threadIdx.x;
    const int wid = tid >> 5, lane = tid & 31;
    __shared__ float2 suw[K_][D_];
    __shared__ float sc1[K_];
    __shared__ float wsum[K_][8];
    float loc[K_];
#pragma unroll
    for (int i = 0; i < K_; i++) {
        int idx = (b * K_ + i) * D_ + tid;
        float sg = g_sig[idx];
        float q  = g_q[idx];
        float w  = 1.0f / fmaf(sg, sg, 1e-8f);
        suw[i][tid] = make_float2(q * w, -0.5f * w);
        loc[i] = logf(fabsf(sg) + 1e-8f) + q * q * w;
    }
#pragma unroll
    for (int i = 0; i < K_; i++) {
        float v = loc[i];
#pragma unroll
        for (int o = 16; o; o >>= 1) v += __shfl_xor_sync(0xffffffffu, v, o);
        if (lane == 0) wsum[i][wid] = v;
    }
    __syncthreads();
    if (tid < K_) {
        float s = 0.f;
#pragma unroll
        for (int j = 0; j < 8; j++) s += wsum[tid][j];
        sc1[tid] = LOGCONST - 0.5f * s;
    }
    __syncthreads();

    const float* kr = g_keys + ((size_t)(b * N_ + n0 + wid * 4)) * D_;
    float acc[4][K_];
#pragma unroll
    for (int r = 0; r < 4; r++)
#pragma unroll
        for (int k = 0; k < K_; k++) acc[r][k] = 0.f;

#pragma unroll
    for (int j = 0; j < 8; j++) {
        int dd = lane + 32 * j;
        float v0 = kr[dd];
        float v1 = kr[D_ + dd];
        float v2 = kr[2 * D_ + dd];
        float v3 = kr[3 * D_ + dd];
        float q0 = v0 * v0, q1 = v1 * v1, q2 = v2 * v2, q3 = v3 * v3;
#pragma unroll
        for (int k = 0; k < K_; k++) {
            float2 uw = suw[k][dd];
            acc[0][k] = fmaf(v0, uw.x, fmaf(q0, uw.y, acc[0][k]));
            acc[1][k] = fmaf(v1, uw.x, fmaf(q1, uw.y, acc[1][k]));
            acc[2][k] = fmaf(v2, uw.x, fmaf(q2, uw.y, acc[2][k]));
            acc[3][k] = fmaf(v3, uw.x, fmaf(q3, uw.y, acc[3][k]));
        }
    }
#pragma unroll
    for (int r = 0; r < 4; r++) {
#pragma unroll
        for (int o = 16; o; o >>= 1)
#pragma unroll
            for (int k = 0; k < K_; k++) acc[r][k] += __shfl_xor_sync(0xffffffffu, acc[r][k], o);
        if (lane == 0) {
            int n = n0 + wid * 4 + r;
#pragma unroll
            for (int k = 0; k < K_; k++) {
                float g = sc1[k] + acc[r][k];
                g = fminf(fmaxf(g, -10000.f), 10000.f);
                g_gll[((size_t)(b * N_ + n)) * K_ + k] = g;
            }
        }
    }
}

// ---------------- softmax reduce over N per (b,k) ----------------
__global__ void k_softmax() {
    int bk = blockIdx.x;
    int b = bk >> 3, k = bk & 7;
    int tid = threadIdx.x;
    __shared__ float red[256];
    float v[16];
    float mx = -3.4e38f;
#pragma unroll
    for (int i = 0; i < 16; i++) {
        int n = tid + (i << 8);
        v[i] = g_gll[((size_t)(b * N_ + n)) * K_ + k];
        mx = fmaxf(mx, v[i]);
    }
    red[tid] = mx; __syncthreads();
    for (int o = 128; o; o >>= 1) { if (tid < o) red[tid] = fmaxf(red[tid], red[tid + o]); __syncthreads(); }
    mx = red[0]; __syncthreads();
    float s = 0.f;
#pragma unroll
    for (int i = 0; i < 16; i++) s += expf(v[i] - mx);
    red[tid] = s; __syncthreads();
    for (int o = 128; o; o >>= 1) { if (tid < o) red[tid] += red[tid + o]; __syncthreads(); }
    if (tid == 0) { g_mx[bk] = mx; g_di[bk] = 1.0f / red[0]; }
}

// ---------------- fused attn + S1/S2 partials (single vals pass) --------------
__global__ __launch_bounds__(256) void k_muS(float* __restrict__ outA, int last) {
    int ch = blockIdx.x, b = blockIdx.y;
    int n0 = ch * CR;
    int tid = threadIdx.x;
    __shared__ __align__(16) float sa[CR][K_];
    __shared__ float sm[K_], sd[K_];
    if (tid < K_) { sm[tid] = g_mx[b * K_ + tid]; sd[tid] = g_di[b * K_ + tid]; }
    __syncthreads();
#pragma unroll
    for (int i = 0; i < 2; i++) {
        int idx = tid + i * 256;
        int nl = idx >> 3, k = idx & 7;
        float g = g_gll[((size_t)(b * N_ + n0 + nl)) * K_ + k];
        sa[nl][k] = expf(g - sm[k]) * sd[k];
    }
    __syncthreads();
    if (last && tid < CR) {
#pragma unroll
        for (int k = 0; k < K_; k++)
            outA[((size_t)(b * K_ + k)) * N_ + n0 + tid] = sa[tid][k];
    }
    int d = tid;
    float a1[K_], a2[K_];
#pragma unroll
    for (int k = 0; k < K_; k++) { a1[k] = 0.f; a2[k] = 0.f; }
    const float* vb = g_vals + ((size_t)(b * N_ + n0)) * D_ + d;
#pragma unroll 4
    for (int nl = 0; nl < CR; nl++) {
        float vv = vb[(size_t)nl * D_];
        float v2 = vv * vv;
        float4 p0 = *(const float4*)&sa[nl][0];
        float4 p1 = *(const float4*)&sa[nl][4];
        a1[0] = fmaf(p0.x, vv, a1[0]); a2[0] = fmaf(p0.x, v2, a2[0]);
        a1[1] = fmaf(p0.y, vv, a1[1]); a2[1] = fmaf(p0.y, v2, a2[1]);
        a1[2] = fmaf(p0.z, vv, a1[2]); a2[2] = fmaf(p0.z, v2, a2[2]);
        a1[3] = fmaf(p0.w, vv, a1[3]); a2[3] = fmaf(p0.w, v2, a2[3]);
        a1[4] = fmaf(p1.x, vv, a1[4]); a2[4] = fmaf(p1.x, v2, a2[4]);
        a1[5] = fmaf(p1.y, vv, a1[5]); a2[5] = fmaf(p1.y, v2, a2[5]);
        a1[6] = fmaf(p1.z, vv, a1[6]); a2[6] = fmaf(p1.z, v2, a2[6]);
        a1[7] = fmaf(p1.w, vv, a1[7]); a2[7] = fmaf(p1.w, v2, a2[7]);
    }
#pragma unroll
    for (int k = 0; k < K_; k++) {
        size_t idx = (((size_t)(b * NCH + ch)) * K_ + k) * D_ + d;
        g_p1[idx] = a1[k];
        g_p2[idx] = a2[k];
    }
}

// ---------------- reduce partials -> mu, sigma = m2 - mu^2 ----------------
__global__ void k_redfin() {
    int k = blockIdx.x, b = blockIdx.y, d = threadIdx.x;
    float s1 = 0.f, s2 = 0.f;
#pragma unroll 8
    for (int c = 0; c < NCH; c++) {
        size_t idx = (((size_t)(b * NCH + c)) * K_ + k) * D_ + d;
        s1 += g_p1[idx];
        s2 += g_p2[idx];
    }
    int o = (b * K_ + k) * D_ + d;
    g_mu[o]  = s1;
    g_sig[o] = fmaf(-s1, s1, s2);
}

// ---------------- final ----------------
__global__ void k_final(const float* __restrict__ nf, float* __restrict__ out) {
    int k = blockIdx.x, b = blockIdx.y, d = threadIdx.x;
    int idx = (b * K_ + k) * D_ + d;
    out[idx] = g_mu[idx] + fmaxf(fabsf(g_sig[idx]), 1e-8f) * nf[idx];
}

// ---------------------------------------------------------------------------
extern "C" void kernel_launch(void* const* d_in, const int* in_sizes, int n_in,
                              void* d_out, int out_size) {
    const float* emb  = (const float*)d_in[0];
    const float* smu  = (const float*)d_in[1];
    const float* sls  = (const float*)d_in[2];
    const float* Wq   = (const float*)d_in[4];
    const float* Wk   = (const float*)d_in[5];
    const float* Wv   = (const float*)d_in[6];
    const float* lnsc = (const float*)d_in[7];
    const float* lnb  = (const float*)d_in[8];
    const float* ni   = (const float*)d_in[9];
    const float* nf   = (const float*)d_in[10];
    float* out      = (float*)d_out;
    float* out_attn = out + B_ * K_ * D_;

    static int smem_set = 0;
    if (!smem_set) {
        cudaFuncSetAttribute(k_gemm_mma, cudaFuncAttributeMaxDynamicSharedMemorySize, GEMM_SMEM);
        smem_set = 1;
    }

    k_lnstats<<<N_ * B_ / 8, 256>>>(emb);
    k_gemm_mma<<<dim3(256, 4), 256, GEMM_SMEM>>>(emb, lnsc, lnb, Wk, Wv);
    k_setup<<<B_ * K_, 256>>>(smu, sls, ni, Wq);

    for (int it = 0; it < 3; it++) {
        int last = (it == 2) ? 1 : 0;
        k_gll<<<dim3(N_ / 32, B_), 256>>>();
        k_softmax<<<B_ * K_, 256>>>();
        k_muS<<<dim3(NCH, B_), 256>>>(out_attn, last);
        k_redfin<<<dim3(K_, B_), 256>>>();
    }
    k_final<<<dim3(K_, B_), 256>>>(nf, out);
}

// round 13
// speedup vs baseline: 1.7170x; 1.0412x over previous
#include <cuda_runtime.h>
#include <math.h>

typedef unsigned int u32;

#define B_  8
#define N_  4096
#define K_  8
#define D_  256
#define NCH 64
#define CR  64
#define NBLK 128
#define LOGCONST (-235.24826450320013f)

// ---------------- scratch ----------------
__device__ float2 g_lnst[B_ * N_];
__device__ float  g_keys[B_ * N_ * D_];
__device__ float  g_vals[B_ * N_ * D_];
__device__ float  g_gll [B_ * N_ * K_];
__device__ float  g_q   [B_ * K_ * D_];
__device__ float  g_sig [B_ * K_ * D_];
__device__ float  g_mu  [B_ * K_ * D_];
__device__ float  g_mx  [B_ * K_];
__device__ float  g_di  [B_ * K_];
__device__ float  g_bmax[B_ * K_ * NBLK];
__device__ float  g_bsum[B_ * K_ * NBLK];
__device__ float  g_p1  [B_ * NCH * K_ * D_];
__device__ float  g_p2  [B_ * NCH * K_ * D_];

// ---------------- LayerNorm row stats ----------------
__global__ void k_lnstats(const float* __restrict__ emb) {
    int warp = threadIdx.x >> 5, lane = threadIdx.x & 31;
    int row  = blockIdx.x * 8 + warp;
    const float* base = emb + (size_t)row * D_;
    float s = 0.f, sq = 0.f;
#pragma unroll
    for (int j = 0; j < 8; j++) {
        float v = base[lane + 32 * j];
        s += v;
        sq = fmaf(v, v, sq);
    }
#pragma unroll
    for (int o = 16; o; o >>= 1) {
        s  += __shfl_xor_sync(0xffffffffu, s,  o);
        sq += __shfl_xor_sync(0xffffffffu, sq, o);
    }
    if (lane == 0) {
        float mean = s * (1.0f / D_);
        float var  = sq * (1.0f / D_) - mean * mean;
        g_lnst[row] = make_float2(mean, 1.0f / sqrtf(var + 1e-5f));
    }
}

// ============ tf32x3 GEMM via mma.sync — double-buffered software pipeline ====
__device__ __forceinline__ void mma8(float* c, const u32* a, const u32* b) {
    asm volatile(
        "mma.sync.aligned.m16n8k8.row.col.f32.tf32.tf32.f32 "
        "{%0,%1,%2,%3}, {%4,%5,%6,%7}, {%8,%9}, {%0,%1,%2,%3};"
        : "+f"(c[0]), "+f"(c[1]), "+f"(c[2]), "+f"(c[3])
        : "r"(a[0]), "r"(a[1]), "r"(a[2]), "r"(a[3]), "r"(b[0]), "r"(b[1]));
}
__device__ __forceinline__ u32 to_tf32(float x) {
    u32 r;
    asm("cvt.rna.tf32.f32 %0, %1;" : "=r"(r) : "f"(x));
    return r;
}

#define PADK 36
#define SMA (128 * PADK)
#define GEMM_SMEM (2 * 4 * SMA * 4)

__global__ __launch_bounds__(256, 1) void k_gemm_mma(const float* __restrict__ emb,
                                                     const float* __restrict__ lnsc,
                                                     const float* __restrict__ lnb,
                                                     const float* __restrict__ Wk,
                                                     const float* __restrict__ Wv) {
    extern __shared__ float sh[];
    const int tid = threadIdx.x, lane = tid & 31, wid = tid >> 5;
    const int m0 = blockIdx.x * 128;
    const int nq = blockIdx.y;
    const float* Bsrc = (nq < 2) ? Wk : Wv;
    float* outp = (nq < 2) ? g_keys : g_vals;
    const int n0 = (nq & 1) * 128;
    const int wm = wid >> 2, wn = wid & 3;
    const int g = lane >> 2, tt = lane & 3;

    const int aRow = tid >> 3;          // 0..31 (i adds 32)
    const int sg   = (tid & 7) * 4;

    float2 st[4];
#pragma unroll
    for (int i = 0; i < 4; i++) st[i] = g_lnst[m0 + aRow + 32 * i];

    float4 ra[4], rb[4], rsc, rbi;

    float acc[4][4][4];
#pragma unroll
    for (int i = 0; i < 4; i++)
#pragma unroll
        for (int j = 0; j < 4; j++)
#pragma unroll
            for (int r = 0; r < 4; r++) acc[i][j][r] = 0.f;

    // ---- stage loads for chunk kc ----
    auto ldgs = [&](int kc) {
        const int k0 = kc * 32;
#pragma unroll
        for (int i = 0; i < 4; i++) {
            ra[i] = *(const float4*)&emb [(size_t)(m0 + aRow + 32 * i) * D_ + k0 + sg];
            rb[i] = *(const float4*)&Bsrc[(size_t)(n0 + aRow + 32 * i) * D_ + k0 + sg];
        }
        rsc = *(const float4*)&lnsc[k0 + sg];
        rbi = *(const float4*)&lnb [k0 + sg];
    };
    // ---- convert staged regs -> smem buffer ----
    auto cvst = [&](int buf) {
        float* Ah = sh + buf * 4 * SMA;
        float* Al = Ah + SMA;
        float* Bh = Ah + 2 * SMA;
        float* Bl = Ah + 3 * SMA;
#pragma unroll
        for (int i = 0; i < 4; i++) {
            int row = aRow + 32 * i;
            float x[4];
            x[0] = fmaf((ra[i].x - st[i].x) * st[i].y, rsc.x, rbi.x);
            x[1] = fmaf((ra[i].y - st[i].x) * st[i].y, rsc.y, rbi.y);
            x[2] = fmaf((ra[i].z - st[i].x) * st[i].y, rsc.z, rbi.z);
            x[3] = fmaf((ra[i].w - st[i].x) * st[i].y, rsc.w, rbi.w);
            u32 hb[4], lb[4];
#pragma unroll
            for (int j = 0; j < 4; j++) {
                hb[j] = __float_as_uint(x[j]) & 0xffffe000u;
                lb[j] = to_tf32(x[j] - __uint_as_float(hb[j]));
            }
            *(float4*)&Ah[row * PADK + sg] =
                make_float4(__uint_as_float(hb[0]), __uint_as_float(hb[1]),
                            __uint_as_float(hb[2]), __uint_as_float(hb[3]));
            *(float4*)&Al[row * PADK + sg] =
                make_float4(__uint_as_float(lb[0]), __uint_as_float(lb[1]),
                            __uint_as_float(lb[2]), __uint_as_float(lb[3]));
            float y[4] = {rb[i].x, rb[i].y, rb[i].z, rb[i].w};
#pragma unroll
            for (int j = 0; j < 4; j++) {
                hb[j] = __float_as_uint(y[j]) & 0xffffe000u;
                lb[j] = to_tf32(y[j] - __uint_as_float(hb[j]));
            }
            *(float4*)&Bh[row * PADK + sg] =
                make_float4(__uint_as_float(hb[0]), __uint_as_float(hb[1]),
                            __uint_as_float(hb[2]), __uint_as_float(hb[3]));
            *(float4*)&Bl[row * PADK + sg] =
                make_float4(__uint_as_float(lb[0]), __uint_as_float(lb[1]),
                            __uint_as_float(lb[2]), __uint_as_float(lb[3]));
        }
    };
    // ---- MMA over one smem buffer ----
    auto mmab = [&](int buf) {
        float* Ah = sh + buf * 4 * SMA;
        float* Al = Ah + SMA;
        float* Bh = Ah + 2 * SMA;
        float* Bl = Ah + 3 * SMA;
#pragma unroll
        for (int ks = 0; ks < 4; ks++) {
            const int kk = ks * 8;
            u32 ah[4][4], al[4][4], bh[4][2], bl[4][2];
#pragma unroll
            for (int mt = 0; mt < 4; mt++) {
                int r = wm * 64 + mt * 16;
                ah[mt][0] = __float_as_uint(Ah[(r + g    ) * PADK + kk + tt    ]);
                ah[mt][1] = __float_as_uint(Ah[(r + g + 8) * PADK + kk + tt    ]);
                ah[mt][2] = __float_as_uint(Ah[(r + g    ) * PADK + kk + tt + 4]);
                ah[mt][3] = __float_as_uint(Ah[(r + g + 8) * PADK + kk + tt + 4]);
                al[mt][0] = __float_as_uint(Al[(r + g    ) * PADK + kk + tt    ]);
                al[mt][1] = __float_as_uint(Al[(r + g + 8) * PADK + kk + tt    ]);
                al[mt][2] = __float_as_uint(Al[(r + g    ) * PADK + kk + tt + 4]);
                al[mt][3] = __float_as_uint(Al[(r + g + 8) * PADK + kk + tt + 4]);
            }
#pragma unroll
            for (int nt = 0; nt < 4; nt++) {
                int c = wn * 32 + nt * 8;
                bh[nt][0] = __float_as_uint(Bh[(c + g) * PADK + kk + tt    ]);
                bh[nt][1] = __float_as_uint(Bh[(c + g) * PADK + kk + tt + 4]);
                bl[nt][0] = __float_as_uint(Bl[(c + g) * PADK + kk + tt    ]);
                bl[nt][1] = __float_as_uint(Bl[(c + g) * PADK + kk + tt + 4]);
            }
#pragma unroll
            for (int mt = 0; mt < 4; mt++)
#pragma unroll
                for (int nt = 0; nt < 4; nt++) {
                    mma8(acc[mt][nt], ah[mt], bh[nt]);
                    mma8(acc[mt][nt], ah[mt], bl[nt]);
                    mma8(acc[mt][nt], al[mt], bh[nt]);
                }
        }
    };

    // prologue
    ldgs(0);
    cvst(0);
    __syncthreads();
    // pipelined main loop
    for (int kc = 0; kc < 8; kc++) {
        if (kc < 7) ldgs(kc + 1);        // LDG issue overlaps the MMA block
        mmab(kc & 1);
        if (kc < 7) cvst((kc + 1) & 1);  // other buffer; safe pre-sync
        __syncthreads();
    }

    // epilogue
#pragma unroll
    for (int mt = 0; mt < 4; mt++) {
        int r = m0 + wm * 64 + mt * 16;
#pragma unroll
        for (int nt = 0; nt < 4; nt++) {
            int c = n0 + wn * 32 + nt * 8 + 2 * tt;
            *(float2*)&outp[(size_t)(r + g    ) * D_ + c] = make_float2(acc[mt][nt][0], acc[mt][nt][1]);
            *(float2*)&outp[(size_t)(r + g + 8) * D_ + c] = make_float2(acc[mt][nt][2], acc[mt][nt][3]);
        }
    }
}

// ---------------- setup: sigma init + queries ----------------
__global__ __launch_bounds__(256) void k_setup(const float* __restrict__ smu,
                                               const float* __restrict__ sls,
                                               const float* __restrict__ ni,
                                               const float* __restrict__ Wq) {
    int bk = blockIdx.x;
    int b = bk >> 3, k = bk & 7;
    int tid = threadIdx.x, wid = tid >> 5, lane = tid & 31;
    __shared__ float ss[D_];
    float sg   = expf(sls[k * D_ + tid]);
    float slot = smu[k * D_ + tid] + sg * ni[(b * K_ + k) * D_ + tid];
    ss[tid] = slot;
    g_sig[(b * K_ + k) * D_ + tid] = sg;
    __syncthreads();
    for (int j = 0; j < 32; j++) {
        int d = wid * 32 + j;
        const float* wr = Wq + (size_t)d * D_;
        float s = 0.f;
#pragma unroll
        for (int c = 0; c < 8; c++) s = fmaf(wr[lane + 32 * c], ss[lane + 32 * c], s);
#pragma unroll
        for (int o = 16; o; o >>= 1) s += __shfl_xor_sync(0xffffffffu, s, o);
        if (lane == 0) g_q[(b * K_ + k) * D_ + d] = s;
    }
}

// ------- gll: 4 rows/warp + per-block softmax partials (max, sum-exp) --------
__global__ __launch_bounds__(256) void k_gll() {
    const int b  = blockIdx.y;
    const int n0 = blockIdx.x * 32;
    const int tid = threadIdx.x;
    const int wid = tid >> 5, lane = tid & 31;
    __shared__ float2 suw[K_][D_];
    __shared__ float sc1[K_];
    __shared__ float wsum[K_][8];
    __shared__ float sgv[32][K_];
    float loc[K_];
#pragma unroll
    for (int i = 0; i < K_; i++) {
        int idx = (b * K_ + i) * D_ + tid;
        float sg = g_sig[idx];
        float q  = g_q[idx];
        float w  = 1.0f / fmaf(sg, sg, 1e-8f);
        suw[i][tid] = make_float2(q * w, -0.5f * w);
        loc[i] = logf(fabsf(sg) + 1e-8f) + q * q * w;
    }
#pragma unroll
    for (int i = 0; i < K_; i++) {
        float v = loc[i];
#pragma unroll
        for (int o = 16; o; o >>= 1) v += __shfl_xor_sync(0xffffffffu, v, o);
        if (lane == 0) wsum[i][wid] = v;
    }
    __syncthreads();
    if (tid < K_) {
        float s = 0.f;
#pragma unroll
        for (int j = 0; j < 8; j++) s += wsum[tid][j];
        sc1[tid] = LOGCONST - 0.5f * s;
    }
    __syncthreads();

    const float* kr = g_keys + ((size_t)(b * N_ + n0 + wid * 4)) * D_;
    float acc[4][K_];
#pragma unroll
    for (int r = 0; r < 4; r++)
#pragma unroll
        for (int k = 0; k < K_; k++) acc[r][k] = 0.f;

#pragma unroll
    for (int j = 0; j < 8; j++) {
        int dd = lane + 32 * j;
        float v0 = kr[dd];
        float v1 = kr[D_ + dd];
        float v2 = kr[2 * D_ + dd];
        float v3 = kr[3 * D_ + dd];
        float q0 = v0 * v0, q1 = v1 * v1, q2 = v2 * v2, q3 = v3 * v3;
#pragma unroll
        for (int k = 0; k < K_; k++) {
            float2 uw = suw[k][dd];
            acc[0][k] = fmaf(v0, uw.x, fmaf(q0, uw.y, acc[0][k]));
            acc[1][k] = fmaf(v1, uw.x, fmaf(q1, uw.y, acc[1][k]));
            acc[2][k] = fmaf(v2, uw.x, fmaf(q2, uw.y, acc[2][k]));
            acc[3][k] = fmaf(v3, uw.x, fmaf(q3, uw.y, acc[3][k]));
        }
    }
#pragma unroll
    for (int r = 0; r < 4; r++) {
#pragma unroll
        for (int o = 16; o; o >>= 1)
#pragma unroll
            for (int k = 0; k < K_; k++) acc[r][k] += __shfl_xor_sync(0xffffffffu, acc[r][k], o);
        if (lane == 0) {
            int n = n0 + wid * 4 + r;
#pragma unroll
            for (int k = 0; k < K_; k++) {
                float g = sc1[k] + acc[r][k];
                g = fminf(fmaxf(g, -10000.f), 10000.f);
                g_gll[((size_t)(b * N_ + n)) * K_ + k] = g;
                sgv[wid * 4 + r][k] = g;
            }
        }
    }
    __syncthreads();
    if (tid < K_) {
        float m = -3.4e38f;
#pragma unroll
        for (int i = 0; i < 32; i++) m = fmaxf(m, sgv[i][tid]);
        float s = 0.f;
#pragma unroll
        for (int i = 0; i < 32; i++) s += expf(sgv[i][tid] - m);
        g_bmax[(b * K_ + tid) * NBLK + blockIdx.x] = m;
        g_bsum[(b * K_ + tid) * NBLK + blockIdx.x] = s;
    }
}

// ---------------- combine per-block partials -> global (mx, 1/sum) -----------
__global__ void k_comb() {
    int bk = blockIdx.x;
    int tid = threadIdx.x;    // 128
    __shared__ float rm[128], rs[128];
    float m = g_bmax[bk * NBLK + tid];
    float s = g_bsum[bk * NBLK + tid];
    rm[tid] = m; __syncthreads();
    for (int o = 64; o; o >>= 1) { if (tid < o) rm[tid] = fmaxf(rm[tid], rm[tid + o]); __syncthreads(); }
    float M = rm[0];
    rs[tid] = s * expf(m - M); __syncthreads();
    for (int o = 64; o; o >>= 1) { if (tid < o) rs[tid] += rs[tid + o]; __syncthreads(); }
    if (tid == 0) { g_mx[bk] = M; g_di[bk] = 1.0f / rs[0]; }
}

// ---------------- fused attn + S1/S2 partials (single vals pass) --------------
__global__ __launch_bounds__(256) void k_muS(float* __restrict__ outA, int last) {
    int ch = blockIdx.x, b = blockIdx.y;
    int n0 = ch * CR;
    int tid = threadIdx.x;
    __shared__ __align__(16) float sa[CR][K_];
    __shared__ float sm[K_], sd[K_];
    if (tid < K_) { sm[tid] = g_mx[b * K_ + tid]; sd[tid] = g_di[b * K_ + tid]; }
    __syncthreads();
#pragma unroll
    for (int i = 0; i < 2; i++) {
        int idx = tid + i * 256;
        int nl = idx >> 3, k = idx & 7;
        float g = g_gll[((size_t)(b * N_ + n0 + nl)) * K_ + k];
        sa[nl][k] = expf(g - sm[k]) * sd[k];
    }
    __syncthreads();
    if (last && tid < CR) {
#pragma unroll
        for (int k = 0; k < K_; k++)
            outA[((size_t)(b * K_ + k)) * N_ + n0 + tid] = sa[tid][k];
    }
    int d = tid;
    float a1[K_], a2[K_];
#pragma unroll
    for (int k = 0; k < K_; k++) { a1[k] = 0.f; a2[k] = 0.f; }
    const float* vb = g_vals + ((size_t)(b * N_ + n0)) * D_ + d;
#pragma unroll 4
    for (int nl = 0; nl < CR; nl++) {
        float vv = vb[(size_t)nl * D_];
        float v2 = vv * vv;
        float4 p0 = *(const float4*)&sa[nl][0];
        float4 p1 = *(const float4*)&sa[nl][4];
        a1[0] = fmaf(p0.x, vv, a1[0]); a2[0] = fmaf(p0.x, v2, a2[0]);
        a1[1] = fmaf(p0.y, vv, a1[1]); a2[1] = fmaf(p0.y, v2, a2[1]);
        a1[2] = fmaf(p0.z, vv, a1[2]); a2[2] = fmaf(p0.z, v2, a2[2]);
        a1[3] = fmaf(p0.w, vv, a1[3]); a2[3] = fmaf(p0.w, v2, a2[3]);
        a1[4] = fmaf(p1.x, vv, a1[4]); a2[4] = fmaf(p1.x, v2, a2[4]);
        a1[5] = fmaf(p1.y, vv, a1[5]); a2[5] = fmaf(p1.y, v2, a2[5]);
        a1[6] = fmaf(p1.z, vv, a1[6]); a2[6] = fmaf(p1.z, v2, a2[6]);
        a1[7] = fmaf(p1.w, vv, a1[7]); a2[7] = fmaf(p1.w, v2, a2[7]);
    }
#pragma unroll
    for (int k = 0; k < K_; k++) {
        size_t idx = (((size_t)(b * NCH + ch)) * K_ + k) * D_ + d;
        g_p1[idx] = a1[k];
        g_p2[idx] = a2[k];
    }
}

// ---------------- reduce partials -> mu, sigma = m2 - mu^2 ----------------
__global__ void k_redfin() {
    int k = blockIdx.x, b = blockIdx.y, d = threadIdx.x;
    float s1 = 0.f, s2 = 0.f;
#pragma unroll 8
    for (int c = 0; c < NCH; c++) {
        size_t idx = (((size_t)(b * NCH + c)) * K_ + k) * D_ + d;
        s1 += g_p1[idx];
        s2 += g_p2[idx];
    }
    int o = (b * K_ + k) * D_ + d;
    g_mu[o]  = s1;
    g_sig[o] = fmaf(-s1, s1, s2);
}

// ---------------- final ----------------
__global__ void k_final(const float* __restrict__ nf, float* __restrict__ out) {
    int k = blockIdx.x, b = blockIdx.y, d = threadIdx.x;
    int idx = (b * K_ + k) * D_ + d;
    out[idx] = g_mu[idx] + fmaxf(fabsf(g_sig[idx]), 1e-8f) * nf[idx];
}

// ---------------------------------------------------------------------------
extern "C" void kernel_launch(void* const* d_in, const int* in_sizes, int n_in,
                              void* d_out, int out_size) {
    const float* emb  = (const float*)d_in[0];
    const float* smu  = (const float*)d_in[1];
    const float* sls  = (const float*)d_in[2];
    const float* Wq   = (const float*)d_in[4];
    const float* Wk   = (const float*)d_in[5];
    const float* Wv   = (const float*)d_in[6];
    const float* lnsc = (const float*)d_in[7];
    const float* lnb  = (const float*)d_in[8];
    const float* ni   = (const float*)d_in[9];
    const float* nf   = (const float*)d_in[10];
    float* out      = (float*)d_out;
    float* out_attn = out + B_ * K_ * D_;

    static int smem_set = 0;
    if (!smem_set) {
        cudaFuncSetAttribute(k_gemm_mma, cudaFuncAttributeMaxDynamicSharedMemorySize, GEMM_SMEM);
        smem_set = 1;
    }

    k_lnstats<<<N_ * B_ / 8, 256>>>(emb);
    k_gemm_mma<<<dim3(256, 4), 256, GEMM_SMEM>>>(emb, lnsc, lnb, Wk, Wv);
    k_setup<<<B_ * K_, 256>>>(smu, sls, ni, Wq);

    for (int it = 0; it < 3; it++) {
        int last = (it == 2) ? 1 : 0;
        k_gll<<<dim3(N_ / 32, B_), 256>>>();
        k_comb<<<B_ * K_, 128>>>();
        k_muS<<<dim3(NCH, B_), 256>>>(out_attn, last);
        k_redfin<<<dim3(K_, B_), 256>>>();
    }
    k_final<<<dim3(K_, B_), 256>>>(nf, out);
}

// round 14
// speedup vs baseline: 1.8225x; 1.0614x over previous
#include <cuda_runtime.h>
#include <cuda_bf16.h>
#include <math.h>

typedef unsigned int u32;

#define B_  8
#define N_  4096
#define K_  8
#define D_  256
#define NCH 64
#define CR  64
#define NBLK 64
#define LOGCONST (-235.24826450320013f)

// ---------------- scratch ----------------
__device__ float2 g_lnst[B_ * N_];
__device__ float  g_keys[B_ * N_ * D_];
__device__ float  g_vals[B_ * N_ * D_];
__device__ float  g_gll [B_ * N_ * K_];
__device__ float  g_q   [B_ * K_ * D_];
__device__ float  g_sig [B_ * K_ * D_];
__device__ float  g_mu  [B_ * K_ * D_];
__device__ float  g_mx  [B_ * K_];
__device__ float  g_di  [B_ * K_];
__device__ float  g_bmax[B_ * K_ * NBLK];
__device__ float  g_bsum[B_ * K_ * NBLK];
__device__ float  g_p1  [B_ * NCH * K_ * D_];
__device__ float  g_p2  [B_ * NCH * K_ * D_];

__device__ __forceinline__ u32 smem_u32(const void* p) {
    u32 a;
    asm("{ .reg .u64 t; cvta.to.shared.u64 t, %1; cvt.u32.u64 %0, t; }" : "=r"(a) : "l"(p));
    return a;
}

// ---------------- LayerNorm row stats ----------------
__global__ void k_lnstats(const float* __restrict__ emb) {
    int warp = threadIdx.x >> 5, lane = threadIdx.x & 31;
    int row  = blockIdx.x * 8 + warp;
    const float* base = emb + (size_t)row * D_;
    float s = 0.f, sq = 0.f;
#pragma unroll
    for (int j = 0; j < 8; j++) {
        float v = base[lane + 32 * j];
        s += v;
        sq = fmaf(v, v, sq);
    }
#pragma unroll
    for (int o = 16; o; o >>= 1) {
        s  += __shfl_xor_sync(0xffffffffu, s,  o);
        sq += __shfl_xor_sync(0xffffffffu, sq, o);
    }
    if (lane == 0) {
        float mean = s * (1.0f / D_);
        float var  = sq * (1.0f / D_) - mean * mean;
        g_lnst[row] = make_float2(mean, 1.0f / sqrtf(var + 1e-5f));
    }
}

// ===== bf16x3 GEMM: mma.m16n8k16 + ldmatrix, double-buffered pipeline =====
__device__ __forceinline__ void mma16(float* c, const u32* a, u32 b0, u32 b1) {
    asm volatile(
        "mma.sync.aligned.m16n8k16.row.col.f32.bf16.bf16.f32 "
        "{%0,%1,%2,%3}, {%4,%5,%6,%7}, {%8,%9}, {%0,%1,%2,%3};"
        : "+f"(c[0]), "+f"(c[1]), "+f"(c[2]), "+f"(c[3])
        : "r"(a[0]), "r"(a[1]), "r"(a[2]), "r"(a[3]), "r"(b0), "r"(b1));
}
#define LDSM_X4(r, addr) \
    asm volatile("ldmatrix.sync.aligned.m8n8.x4.shared.b16 {%0,%1,%2,%3}, [%4];" \
        : "=r"((r)[0]), "=r"((r)[1]), "=r"((r)[2]), "=r"((r)[3]) : "r"(addr))

__device__ __forceinline__ u32 packbf(float a, float b) {
    __nv_bfloat162 v = __floats2bfloat162_rn(a, b);
    return *(u32*)&v;
}

#define ROWB 80                 // bytes per 32-k bf16 row (40 elems, padded)
#define PLANE 10240             // 128 rows * 80 B
#define BUFB  (4 * PLANE)       // Ah Am Bh Bm
#define GEMM_SMEM (2 * BUFB)    // 80 KB

__global__ __launch_bounds__(256, 1) void k_gemm_mma(const float* __restrict__ emb,
                                                     const float* __restrict__ lnsc,
                                                     const float* __restrict__ lnb,
                                                     const float* __restrict__ Wk,
                                                     const float* __restrict__ Wv) {
    extern __shared__ char smc[];
    const u32 sb = smem_u32(smc);
    const int tid = threadIdx.x, lane = tid & 31, wid = tid >> 5;
    const int m0 = blockIdx.x * 128;
    const int nq = blockIdx.y;
    const float* Bsrc = (nq < 2) ? Wk : Wv;
    float* outp = (nq < 2) ? g_keys : g_vals;
    const int n0 = (nq & 1) * 128;
    const int wm = wid >> 2, wn = wid & 3;
    const int g = lane >> 2, tt = lane & 3;

    const int aRow = tid >> 3;            // 0..31 (+32*i)
    const int sg   = (tid & 7) * 4;       // k offset (4 elems)

    float2 st[4];
#pragma unroll
    for (int i = 0; i < 4; i++) st[i] = g_lnst[m0 + aRow + 32 * i];

    float4 ra[4], rb[4], rsc, rbi;

    float acc[4][4][4];
#pragma unroll
    for (int i = 0; i < 4; i++)
#pragma unroll
        for (int j = 0; j < 4; j++)
#pragma unroll
            for (int r = 0; r < 4; r++) acc[i][j][r] = 0.f;

    auto ldgs = [&](int kc) {
        const int k0 = kc * 32;
#pragma unroll
        for (int i = 0; i < 4; i++) {
            ra[i] = *(const float4*)&emb [(size_t)(m0 + aRow + 32 * i) * D_ + k0 + sg];
            rb[i] = *(const float4*)&Bsrc[(size_t)(n0 + aRow + 32 * i) * D_ + k0 + sg];
        }
        rsc = *(const float4*)&lnsc[k0 + sg];
        rbi = *(const float4*)&lnb [k0 + sg];
    };

    auto cvst = [&](int buf) {
        char* Ah = smc + buf * BUFB;
        char* Am = Ah + PLANE;
        char* Bh = Ah + 2 * PLANE;
        char* Bm = Ah + 3 * PLANE;
#pragma unroll
        for (int i = 0; i < 4; i++) {
            int off = (aRow + 32 * i) * ROWB + sg * 2;
            // ---- A with LN ----
            float x0 = fmaf((ra[i].x - st[i].x) * st[i].y, rsc.x, rbi.x);
            float x1 = fmaf((ra[i].y - st[i].x) * st[i].y, rsc.y, rbi.y);
            float x2 = fmaf((ra[i].z - st[i].x) * st[i].y, rsc.z, rbi.z);
            float x3 = fmaf((ra[i].w - st[i].x) * st[i].y, rsc.w, rbi.w);
            u32 h01 = packbf(x0, x1), h23 = packbf(x2, x3);
            float m0f = x0 - __uint_as_float(h01 << 16);
            float m1f = x1 - __uint_as_float(h01 & 0xffff0000u);
            float m2f = x2 - __uint_as_float(h23 << 16);
            float m3f = x3 - __uint_as_float(h23 & 0xffff0000u);
            *(uint2*)(Ah + off) = make_uint2(h01, h23);
            *(uint2*)(Am + off) = make_uint2(packbf(m0f, m1f), packbf(m2f, m3f));
            // ---- B ----
            u32 g01 = packbf(rb[i].x, rb[i].y), g23 = packbf(rb[i].z, rb[i].w);
            float n0f = rb[i].x - __uint_as_float(g01 << 16);
            float n1f = rb[i].y - __uint_as_float(g01 & 0xffff0000u);
            float n2f = rb[i].z - __uint_as_float(g23 << 16);
            float n3f = rb[i].w - __uint_as_float(g23 & 0xffff0000u);
            *(uint2*)(Bh + off) = make_uint2(g01, g23);
            *(uint2*)(Bm + off) = make_uint2(packbf(n0f, n1f), packbf(n2f, n3f));
        }
    };

    const u32 laneoff = ((lane & 7) + (lane & 8)) * ROWB + ((lane & 16) ? 16 : 0);

    auto mmab = [&](int buf) {
        const u32 base = sb + buf * BUFB;
#pragma unroll
        for (int ks = 0; ks < 2; ks++) {
            const u32 kb = ks * 32;    // 16 bf16 = 32 bytes
            u32 ah[4][4], am[4][4], bh[2][4], bm[2][4];
#pragma unroll
            for (int mt = 0; mt < 4; mt++) {
                u32 addr = base + (u32)(wm * 64 + mt * 16) * ROWB + kb + laneoff;
                LDSM_X4(ah[mt], addr);
                LDSM_X4(am[mt], addr + PLANE);
            }
#pragma unroll
            for (int np = 0; np < 2; np++) {
                u32 addr = base + 2 * PLANE + (u32)(wn * 32 + np * 16) * ROWB + kb + laneoff;
                LDSM_X4(bh[np], addr);
                LDSM_X4(bm[np], addr + PLANE);
            }
#pragma unroll
            for (int mt = 0; mt < 4; mt++)
#pragma unroll
                for (int nt = 0; nt < 4; nt++) {
                    int np = nt >> 1, sl = nt & 1;
                    mma16(acc[mt][nt], ah[mt], bh[np][sl], bh[np][sl + 2]);
                    mma16(acc[mt][nt], ah[mt], bm[np][sl], bm[np][sl + 2]);
                    mma16(acc[mt][nt], am[mt], bh[np][sl], bh[np][sl + 2]);
                }
        }
    };

    ldgs(0);
    cvst(0);
    __syncthreads();
    for (int kc = 0; kc < 8; kc++) {
        if (kc < 7) ldgs(kc + 1);
        mmab(kc & 1);
        if (kc < 7) cvst((kc + 1) & 1);
        __syncthreads();
    }

#pragma unroll
    for (int mt = 0; mt < 4; mt++) {
        int r = m0 + wm * 64 + mt * 16;
#pragma unroll
        for (int nt = 0; nt < 4; nt++) {
            int c = n0 + wn * 32 + nt * 8 + 2 * tt;
            *(float2*)&outp[(size_t)(r + g    ) * D_ + c] = make_float2(acc[mt][nt][0], acc[mt][nt][1]);
            *(float2*)&outp[(size_t)(r + g + 8) * D_ + c] = make_float2(acc[mt][nt][2], acc[mt][nt][3]);
        }
    }
}

// ---------------- setup: sigma init + queries ----------------
__global__ __launch_bounds__(256) void k_setup(const float* __restrict__ smu,
                                               const float* __restrict__ sls,
                                               const float* __restrict__ ni,
                                               const float* __restrict__ Wq) {
    int bk = blockIdx.x;
    int b = bk >> 3, k = bk & 7;
    int tid = threadIdx.x, wid = tid >> 5, lane = tid & 31;
    __shared__ float ss[D_];
    float sg   = expf(sls[k * D_ + tid]);
    float slot = smu[k * D_ + tid] + sg * ni[(b * K_ + k) * D_ + tid];
    ss[tid] = slot;
    g_sig[(b * K_ + k) * D_ + tid] = sg;
    __syncthreads();
    for (int j = 0; j < 32; j++) {
        int d = wid * 32 + j;
        const float* wr = Wq + (size_t)d * D_;
        float s = 0.f;
#pragma unroll
        for (int c = 0; c < 8; c++) s = fmaf(wr[lane + 32 * c], ss[lane + 32 * c], s);
#pragma unroll
        for (int o = 16; o; o >>= 1) s += __shfl_xor_sync(0xffffffffu, s, o);
        if (lane == 0) g_q[(b * K_ + k) * D_ + d] = s;
    }
}

// ------- gll: 8 rows/warp + per-block softmax partials ----------------------
__global__ __launch_bounds__(256) void k_gll() {
    const int b  = blockIdx.y;
    const int n0 = blockIdx.x * 64;
    const int tid = threadIdx.x;
    const int wid = tid >> 5, lane = tid & 31;
    __shared__ float2 suw[K_][D_];
    __shared__ float sc1[K_];
    __shared__ float wsum[K_][8];
    __shared__ float sgv[64][K_];
    float loc[K_];
#pragma unroll
    for (int i = 0; i < K_; i++) {
        int idx = (b * K_ + i) * D_ + tid;
        float sg = g_sig[idx];
        float q  = g_q[idx];
        float w  = 1.0f / fmaf(sg, sg, 1e-8f);
        suw[i][tid] = make_float2(q * w, -0.5f * w);
        loc[i] = logf(fabsf(sg) + 1e-8f) + q * q * w;
    }
#pragma unroll
    for (int i = 0; i < K_; i++) {
        float v = loc[i];
#pragma unroll
        for (int o = 16; o; o >>= 1) v += __shfl_xor_sync(0xffffffffu, v, o);
        if (lane == 0) wsum[i][wid] = v;
    }
    __syncthreads();
    if (tid < K_) {
        float s = 0.f;
#pragma unroll
        for (int j = 0; j < 8; j++) s += wsum[tid][j];
        sc1[tid] = LOGCONST - 0.5f * s;
    }
    __syncthreads();

    const float* kr = g_keys + ((size_t)(b * N_ + n0 + wid * 8)) * D_;
    float acc[8][K_];
#pragma unroll
    for (int r = 0; r < 8; r++)
#pragma unroll
        for (int k = 0; k < K_; k++) acc[r][k] = 0.f;

#pragma unroll
    for (int j = 0; j < 8; j++) {
        int dd = lane + 32 * j;
        float v[8], q[8];
#pragma unroll
        for (int r = 0; r < 8; r++) { v[r] = kr[(size_t)r * D_ + dd]; q[r] = v[r] * v[r]; }
#pragma unroll
        for (int k = 0; k < K_; k++) {
            float2 uw = suw[k][dd];
#pragma unroll
            for (int r = 0; r < 8; r++)
                acc[r][k] = fmaf(v[r], uw.x, fmaf(q[r], uw.y, acc[r][k]));
        }
    }
#pragma unroll
    for (int r = 0; r < 8; r++) {
#pragma unroll
        for (int o = 16; o; o >>= 1)
#pragma unroll
            for (int k = 0; k < K_; k++) acc[r][k] += __shfl_xor_sync(0xffffffffu, acc[r][k], o);
        if (lane == 0) {
            int n = n0 + wid * 8 + r;
#pragma unroll
            for (int k = 0; k < K_; k++) {
                float g = sc1[k] + acc[r][k];
                g = fminf(fmaxf(g, -10000.f), 10000.f);
                g_gll[((size_t)(b * N_ + n)) * K_ + k] = g;
                sgv[wid * 8 + r][k] = g;
            }
        }
    }
    __syncthreads();
    if (tid < K_) {
        float m = -3.4e38f;
#pragma unroll
        for (int i = 0; i < 64; i++) m = fmaxf(m, sgv[i][tid]);
        float s = 0.f;
#pragma unroll
        for (int i = 0; i < 64; i++) s += expf(sgv[i][tid] - m);
        g_bmax[(b * K_ + tid) * NBLK + blockIdx.x] = m;
        g_bsum[(b * K_ + tid) * NBLK + blockIdx.x] = s;
    }
}

// ---------------- combine per-block partials ----------------
__global__ void k_comb() {
    int bk = blockIdx.x;
    int tid = threadIdx.x;    // 64
    __shared__ float rm[64], rs[64];
    float m = g_bmax[bk * NBLK + tid];
    float s = g_bsum[bk * NBLK + tid];
    rm[tid] = m; __syncthreads();
    for (int o = 32; o; o >>= 1) { if (tid < o) rm[tid] = fmaxf(rm[tid], rm[tid + o]); __syncthreads(); }
    float M = rm[0];
    rs[tid] = s * expf(m - M); __syncthreads();
    for (int o = 32; o; o >>= 1) { if (tid < o) rs[tid] += rs[tid + o]; __syncthreads(); }
    if (tid == 0) { g_mx[bk] = M; g_di[bk] = 1.0f / rs[0]; }
}

// ---------------- fused attn + S1/S2 partials ----------------
__global__ __launch_bounds__(256) void k_muS(float* __restrict__ outA, int last) {
    int ch = blockIdx.x, b = blockIdx.y;
    int n0 = ch * CR;
    int tid = threadIdx.x;
    __shared__ __align__(16) float sa[CR][K_];
    __shared__ float sm[K_], sd[K_];
    if (tid < K_) { sm[tid] = g_mx[b * K_ + tid]; sd[tid] = g_di[b * K_ + tid]; }
    __syncthreads();
#pragma unroll
    for (int i = 0; i < 2; i++) {
        int idx = tid + i * 256;
        int nl = idx >> 3, k = idx & 7;
        float g = g_gll[((size_t)(b * N_ + n0 + nl)) * K_ + k];
        sa[nl][k] = expf(g - sm[k]) * sd[k];
    }
    __syncthreads();
    if (last && tid < CR) {
#pragma unroll
        for (int k = 0; k < K_; k++)
            outA[((size_t)(b * K_ + k)) * N_ + n0 + tid] = sa[tid][k];
    }
    int d = tid;
    float a1[K_], a2[K_];
#pragma unroll
    for (int k = 0; k < K_; k++) { a1[k] = 0.f; a2[k] = 0.f; }
    const float* vb = g_vals + ((size_t)(b * N_ + n0)) * D_ + d;
#pragma unroll 4
    for (int nl = 0; nl < CR; nl++) {
        float vv = vb[(size_t)nl * D_];
        float v2 = vv * vv;
        float4 p0 = *(const float4*)&sa[nl][0];
        float4 p1 = *(const float4*)&sa[nl][4];
        a1[0] = fmaf(p0.x, vv, a1[0]); a2[0] = fmaf(p0.x, v2, a2[0]);
        a1[1] = fmaf(p0.y, vv, a1[1]); a2[1] = fmaf(p0.y, v2, a2[1]);
        a1[2] = fmaf(p0.z, vv, a1[2]); a2[2] = fmaf(p0.z, v2, a2[2]);
        a1[3] = fmaf(p0.w, vv, a1[3]); a2[3] = fmaf(p0.w, v2, a2[3]);
        a1[4] = fmaf(p1.x, vv, a1[4]); a2[4] = fmaf(p1.x, v2, a2[4]);
        a1[5] = fmaf(p1.y, vv, a1[5]); a2[5] = fmaf(p1.y, v2, a2[5]);
        a1[6] = fmaf(p1.z, vv, a1[6]); a2[6] = fmaf(p1.z, v2, a2[6]);
        a1[7] = fmaf(p1.w, vv, a1[7]); a2[7] = fmaf(p1.w, v2, a2[7]);
    }
#pragma unroll
    for (int k = 0; k < K_; k++) {
        size_t idx = (((size_t)(b * NCH + ch)) * K_ + k) * D_ + d;
        g_p1[idx] = a1[k];
        g_p2[idx] = a2[k];
    }
}

// ---------------- reduce partials -> mu, sigma ----------------
__global__ void k_redfin() {
    int k = blockIdx.x, b = blockIdx.y, d = threadIdx.x;
    float s1 = 0.f, s2 = 0.f;
#pragma unroll 8
    for (int c = 0; c < NCH; c++) {
        size_t idx = (((size_t)(b * NCH + c)) * K_ + k) * D_ + d;
        s1 += g_p1[idx];
        s2 += g_p2[idx];
    }
    int o = (b * K_ + k) * D_ + d;
    g_mu[o]  = s1;
    g_sig[o] = fmaf(-s1, s1, s2);
}

// ---------------- final ----------------
__global__ void k_final(const float* __restrict__ nf, float* __restrict__ out) {
    int k = blockIdx.x, b = blockIdx.y, d = threadIdx.x;
    int idx = (b * K_ + k) * D_ + d;
    out[idx] = g_mu[idx] + fmaxf(fabsf(g_sig[idx]), 1e-8f) * nf[idx];
}

// ---------------------------------------------------------------------------
extern "C" void kernel_launch(void* const* d_in, const int* in_sizes, int n_in,
                              void* d_out, int out_size) {
    const float* emb  = (const float*)d_in[0];
    const float* smu  = (const float*)d_in[1];
    const float* sls  = (const float*)d_in[2];
    const float* Wq   = (const float*)d_in[4];
    const float* Wk   = (const float*)d_in[5];
    const float* Wv   = (const float*)d_in[6];
    const float* lnsc = (const float*)d_in[7];
    const float* lnb  = (const float*)d_in[8];
    const float* ni   = (const float*)d_in[9];
    const float* nf   = (const float*)d_in[10];
    float* out      = (float*)d_out;
    float* out_attn = out + B_ * K_ * D_;

    static int smem_set = 0;
    if (!smem_set) {
        cudaFuncSetAttribute(k_gemm_mma, cudaFuncAttributeMaxDynamicSharedMemorySize, GEMM_SMEM);
        smem_set = 1;
    }

    k_lnstats<<<N_ * B_ / 8, 256>>>(emb);
    k_gemm_mma<<<dim3(256, 4), 256, GEMM_SMEM>>>(emb, lnsc, lnb, Wk, Wv);
    k_setup<<<B_ * K_, 256>>>(smu, sls, ni, Wq);

    for (int it = 0; it < 3; it++) {
        int last = (it == 2) ? 1 : 0;
        k_gll<<<dim3(N_ / 64, B_), 256>>>();
        k_comb<<<B_ * K_, 64>>>();
        k_muS<<<dim3(NCH, B_), 256>>>(out_attn, last);
        k_redfin<<<dim3(K_, B_), 256>>>();
    }
    k_final<<<dim3(K_, B_), 256>>>(nf, out);
}

// round 15
// speedup vs baseline: 1.9194x; 1.0532x over previous
#include <cuda_runtime.h>
#include <cuda_bf16.h>
#include <math.h>

typedef unsigned int u32;

#define B_  8
#define N_  4096
#define K_  8
#define D_  256
#define NCH 64
#define CR  64
#define NBLK 128
#define LOGCONST (-235.24826450320013f)

// ---------------- scratch ----------------
__device__ float2 g_lnst[B_ * N_];
__device__ float  g_keys[B_ * N_ * D_];
__device__ float  g_vals[B_ * N_ * D_];
__device__ float  g_gll [B_ * N_ * K_];
__device__ float  g_q   [B_ * K_ * D_];
__device__ float  g_sig [B_ * K_ * D_];
__device__ float  g_mu  [B_ * K_ * D_];
__device__ float  g_mx  [B_ * K_];
__device__ float  g_di  [B_ * K_];
__device__ float  g_bmax[B_ * K_ * NBLK];
__device__ float  g_bsum[B_ * K_ * NBLK];
__device__ float  g_p1  [B_ * NCH * K_ * D_];
__device__ float  g_p2  [B_ * NCH * K_ * D_];

__device__ __forceinline__ u32 smem_u32(const void* p) {
    u32 a;
    asm("{ .reg .u64 t; cvta.to.shared.u64 t, %1; cvt.u32.u64 %0, t; }" : "=r"(a) : "l"(p));
    return a;
}

// ---------------- LayerNorm row stats ----------------
__global__ void k_lnstats(const float* __restrict__ emb) {
    int warp = threadIdx.x >> 5, lane = threadIdx.x & 31;
    int row  = blockIdx.x * 8 + warp;
    const float* base = emb + (size_t)row * D_;
    float s = 0.f, sq = 0.f;
#pragma unroll
    for (int j = 0; j < 8; j++) {
        float v = base[lane + 32 * j];
        s += v;
        sq = fmaf(v, v, sq);
    }
#pragma unroll
    for (int o = 16; o; o >>= 1) {
        s  += __shfl_xor_sync(0xffffffffu, s,  o);
        sq += __shfl_xor_sync(0xffffffffu, sq, o);
    }
    if (lane == 0) {
        float mean = s * (1.0f / D_);
        float var  = sq * (1.0f / D_) - mean * mean;
        g_lnst[row] = make_float2(mean, 1.0f / sqrtf(var + 1e-5f));
    }
}

// ===== bf16x3 GEMM: mma.m16n8k16 + ldmatrix, double-buffered (proven R14) =====
__device__ __forceinline__ void mma16(float* c, const u32* a, u32 b0, u32 b1) {
    asm volatile(
        "mma.sync.aligned.m16n8k16.row.col.f32.bf16.bf16.f32 "
        "{%0,%1,%2,%3}, {%4,%5,%6,%7}, {%8,%9}, {%0,%1,%2,%3};"
        : "+f"(c[0]), "+f"(c[1]), "+f"(c[2]), "+f"(c[3])
        : "r"(a[0]), "r"(a[1]), "r"(a[2]), "r"(a[3]), "r"(b0), "r"(b1));
}
#define LDSM_X4(r, addr) \
    asm volatile("ldmatrix.sync.aligned.m8n8.x4.shared.b16 {%0,%1,%2,%3}, [%4];" \
        : "=r"((r)[0]), "=r"((r)[1]), "=r"((r)[2]), "=r"((r)[3]) : "r"(addr))

__device__ __forceinline__ u32 packbf(float a, float b) {
    __nv_bfloat162 v = __floats2bfloat162_rn(a, b);
    return *(u32*)&v;
}

#define ROWB 80
#define PLANE 10240
#define BUFB  (4 * PLANE)
#define GEMM_SMEM (2 * BUFB)

__global__ __launch_bounds__(256, 1) void k_gemm_mma(const float* __restrict__ emb,
                                                     const float* __restrict__ lnsc,
                                                     const float* __restrict__ lnb,
                                                     const float* __restrict__ Wk,
                                                     const float* __restrict__ Wv) {
    extern __shared__ char smc[];
    const u32 sb = smem_u32(smc);
    const int tid = threadIdx.x, lane = tid & 31, wid = tid >> 5;
    const int m0 = blockIdx.x * 128;
    const int nq = blockIdx.y;
    const float* Bsrc = (nq < 2) ? Wk : Wv;
    float* outp = (nq < 2) ? g_keys : g_vals;
    const int n0 = (nq & 1) * 128;
    const int wm = wid >> 2, wn = wid & 3;
    const int g = lane >> 2, tt = lane & 3;

    const int aRow = tid >> 3;
    const int sg   = (tid & 7) * 4;

    float2 st[4];
#pragma unroll
    for (int i = 0; i < 4; i++) st[i] = g_lnst[m0 + aRow + 32 * i];

    float4 ra[4], rb[4], rsc, rbi;

    float acc[4][4][4];
#pragma unroll
    for (int i = 0; i < 4; i++)
#pragma unroll
        for (int j = 0; j < 4; j++)
#pragma unroll
            for (int r = 0; r < 4; r++) acc[i][j][r] = 0.f;

    auto ldgs = [&](int kc) {
        const int k0 = kc * 32;
#pragma unroll
        for (int i = 0; i < 4; i++) {
            ra[i] = *(const float4*)&emb [(size_t)(m0 + aRow + 32 * i) * D_ + k0 + sg];
            rb[i] = *(const float4*)&Bsrc[(size_t)(n0 + aRow + 32 * i) * D_ + k0 + sg];
        }
        rsc = *(const float4*)&lnsc[k0 + sg];
        rbi = *(const float4*)&lnb [k0 + sg];
    };

    auto cvst = [&](int buf) {
        char* Ah = smc + buf * BUFB;
        char* Am = Ah + PLANE;
        char* Bh = Ah + 2 * PLANE;
        char* Bm = Ah + 3 * PLANE;
#pragma unroll
        for (int i = 0; i < 4; i++) {
            int off = (aRow + 32 * i) * ROWB + sg * 2;
            float x0 = fmaf((ra[i].x - st[i].x) * st[i].y, rsc.x, rbi.x);
            float x1 = fmaf((ra[i].y - st[i].x) * st[i].y, rsc.y, rbi.y);
            float x2 = fmaf((ra[i].z - st[i].x) * st[i].y, rsc.z, rbi.z);
            float x3 = fmaf((ra[i].w - st[i].x) * st[i].y, rsc.w, rbi.w);
            u32 h01 = packbf(x0, x1), h23 = packbf(x2, x3);
            float m0f = x0 - __uint_as_float(h01 << 16);
            float m1f = x1 - __uint_as_float(h01 & 0xffff0000u);
            float m2f = x2 - __uint_as_float(h23 << 16);
            float m3f = x3 - __uint_as_float(h23 & 0xffff0000u);
            *(uint2*)(Ah + off) = make_uint2(h01, h23);
            *(uint2*)(Am + off) = make_uint2(packbf(m0f, m1f), packbf(m2f, m3f));
            u32 g01 = packbf(rb[i].x, rb[i].y), g23 = packbf(rb[i].z, rb[i].w);
            float n0f = rb[i].x - __uint_as_float(g01 << 16);
            float n1f = rb[i].y - __uint_as_float(g01 & 0xffff0000u);
            float n2f = rb[i].z - __uint_as_float(g23 << 16);
            float n3f = rb[i].w - __uint_as_float(g23 & 0xffff0000u);
            *(uint2*)(Bh + off) = make_uint2(g01, g23);
            *(uint2*)(Bm + off) = make_uint2(packbf(n0f, n1f), packbf(n2f, n3f));
        }
    };

    const u32 laneoff = ((lane & 7) + (lane & 8)) * ROWB + ((lane & 16) ? 16 : 0);

    auto mmab = [&](int buf) {
        const u32 base = sb + buf * BUFB;
#pragma unroll
        for (int ks = 0; ks < 2; ks++) {
            const u32 kb = ks * 32;
            u32 ah[4][4], am[4][4], bh[2][4], bm[2][4];
#pragma unroll
            for (int mt = 0; mt < 4; mt++) {
                u32 addr = base + (u32)(wm * 64 + mt * 16) * ROWB + kb + laneoff;
                LDSM_X4(ah[mt], addr);
                LDSM_X4(am[mt], addr + PLANE);
            }
#pragma unroll
            for (int np = 0; np < 2; np++) {
                u32 addr = base + 2 * PLANE + (u32)(wn * 32 + np * 16) * ROWB + kb + laneoff;
                LDSM_X4(bh[np], addr);
                LDSM_X4(bm[np], addr + PLANE);
            }
#pragma unroll
            for (int mt = 0; mt < 4; mt++)
#pragma unroll
                for (int nt = 0; nt < 4; nt++) {
                    int np = nt >> 1, sl = nt & 1;
                    mma16(acc[mt][nt], ah[mt], bh[np][sl], bh[np][sl + 2]);
                    mma16(acc[mt][nt], ah[mt], bm[np][sl], bm[np][sl + 2]);
                    mma16(acc[mt][nt], am[mt], bh[np][sl], bh[np][sl + 2]);
                }
        }
    };

    ldgs(0);
    cvst(0);
    __syncthreads();
    for (int kc = 0; kc < 8; kc++) {
        if (kc < 7) ldgs(kc + 1);
        mmab(kc & 1);
        if (kc < 7) cvst((kc + 1) & 1);
        __syncthreads();
    }

#pragma unroll
    for (int mt = 0; mt < 4; mt++) {
        int r = m0 + wm * 64 + mt * 16;
#pragma unroll
        for (int nt = 0; nt < 4; nt++) {
            int c = n0 + wn * 32 + nt * 8 + 2 * tt;
            *(float2*)&outp[(size_t)(r + g    ) * D_ + c] = make_float2(acc[mt][nt][0], acc[mt][nt][1]);
            *(float2*)&outp[(size_t)(r + g + 8) * D_ + c] = make_float2(acc[mt][nt][2], acc[mt][nt][3]);
        }
    }
}

// ---------------- setup: sigma init + queries ----------------
__global__ __launch_bounds__(256) void k_setup(const float* __restrict__ smu,
                                               const float* __restrict__ sls,
                                               const float* __restrict__ ni,
                                               const float* __restrict__ Wq) {
    int bk = blockIdx.x;
    int b = bk >> 3, k = bk & 7;
    int tid = threadIdx.x, wid = tid >> 5, lane = tid & 31;
    __shared__ float ss[D_];
    float sg   = expf(sls[k * D_ + tid]);
    float slot = smu[k * D_ + tid] + sg * ni[(b * K_ + k) * D_ + tid];
    ss[tid] = slot;
    g_sig[(b * K_ + k) * D_ + tid] = sg;
    __syncthreads();
    for (int j = 0; j < 32; j++) {
        int d = wid * 32 + j;
        const float* wr = Wq + (size_t)d * D_;
        float s = 0.f;
#pragma unroll
        for (int c = 0; c < 8; c++) s = fmaf(wr[lane + 32 * c], ss[lane + 32 * c], s);
#pragma unroll
        for (int o = 16; o; o >>= 1) s += __shfl_xor_sync(0xffffffffu, s, o);
        if (lane == 0) g_q[(b * K_ + k) * D_ + d] = s;
    }
}

// ------- gll: 4 rows/warp + per-block softmax partials (proven R13) ----------
__global__ __launch_bounds__(256) void k_gll() {
    const int b  = blockIdx.y;
    const int n0 = blockIdx.x * 32;
    const int tid = threadIdx.x;
    const int wid = tid >> 5, lane = tid & 31;
    __shared__ float2 suw[K_][D_];
    __shared__ float sc1[K_];
    __shared__ float wsum[K_][8];
    __shared__ float sgv[32][K_];
    float loc[K_];
#pragma unroll
    for (int i = 0; i < K_; i++) {
        int idx = (b * K_ + i) * D_ + tid;
        float sg = g_sig[idx];
        float q  = g_q[idx];
        float w  = 1.0f / fmaf(sg, sg, 1e-8f);
        suw[i][tid] = make_float2(q * w, -0.5f * w);
        loc[i] = logf(fabsf(sg) + 1e-8f) + q * q * w;
    }
#pragma unroll
    for (int i = 0; i < K_; i++) {
        float v = loc[i];
#pragma unroll
        for (int o = 16; o; o >>= 1) v += __shfl_xor_sync(0xffffffffu, v, o);
        if (lane == 0) wsum[i][wid] = v;
    }
    __syncthreads();
    if (tid < K_) {
        float s = 0.f;
#pragma unroll
        for (int j = 0; j < 8; j++) s += wsum[tid][j];
        sc1[tid] = LOGCONST - 0.5f * s;
    }
    __syncthreads();

    const float* kr = g_keys + ((size_t)(b * N_ + n0 + wid * 4)) * D_;
    float acc[4][K_];
#pragma unroll
    for (int r = 0; r < 4; r++)
#pragma unroll
        for (int k = 0; k < K_; k++) acc[r][k] = 0.f;

#pragma unroll
    for (int j = 0; j < 8; j++) {
        int dd = lane + 32 * j;
        float v0 = kr[dd];
        float v1 = kr[D_ + dd];
        float v2 = kr[2 * D_ + dd];
        float v3 = kr[3 * D_ + dd];
        float q0 = v0 * v0, q1 = v1 * v1, q2 = v2 * v2, q3 = v3 * v3;
#pragma unroll
        for (int k = 0; k < K_; k++) {
            float2 uw = suw[k][dd];
            acc[0][k] = fmaf(v0, uw.x, fmaf(q0, uw.y, acc[0][k]));
            acc[1][k] = fmaf(v1, uw.x, fmaf(q1, uw.y, acc[1][k]));
            acc[2][k] = fmaf(v2, uw.x, fmaf(q2, uw.y, acc[2][k]));
            acc[3][k] = fmaf(v3, uw.x, fmaf(q3, uw.y, acc[3][k]));
        }
    }
#pragma unroll
    for (int r = 0; r < 4; r++) {
#pragma unroll
        for (int o = 16; o; o >>= 1)
#pragma unroll
            for (int k = 0; k < K_; k++) acc[r][k] += __shfl_xor_sync(0xffffffffu, acc[r][k], o);
        if (lane == 0) {
            int n = n0 + wid * 4 + r;
#pragma unroll
            for (int k = 0; k < K_; k++) {
                float g = sc1[k] + acc[r][k];
                g = fminf(fmaxf(g, -10000.f), 10000.f);
                g_gll[((size_t)(b * N_ + n)) * K_ + k] = g;
                sgv[wid * 4 + r][k] = g;
            }
        }
    }
    __syncthreads();
    if (tid < K_) {
        float m = -3.4e38f;
#pragma unroll
        for (int i = 0; i < 32; i++) m = fmaxf(m, sgv[i][tid]);
        float s = 0.f;
#pragma unroll
        for (int i = 0; i < 32; i++) s += expf(sgv[i][tid] - m);
        g_bmax[(b * K_ + tid) * NBLK + blockIdx.x] = m;
        g_bsum[(b * K_ + tid) * NBLK + blockIdx.x] = s;
    }
}

// ---------------- combine per-block partials ----------------
__global__ void k_comb() {
    int bk = blockIdx.x;
    int tid = threadIdx.x;    // 128
    __shared__ float rm[128], rs[128];
    float m = g_bmax[bk * NBLK + tid];
    float s = g_bsum[bk * NBLK + tid];
    rm[tid] = m; __syncthreads();
    for (int o = 64; o; o >>= 1) { if (tid < o) rm[tid] = fmaxf(rm[tid], rm[tid + o]); __syncthreads(); }
    float M = rm[0];
    rs[tid] = s * expf(m - M); __syncthreads();
    for (int o = 64; o; o >>= 1) { if (tid < o) rs[tid] += rs[tid + o]; __syncthreads(); }
    if (tid == 0) { g_mx[bk] = M; g_di[bk] = 1.0f / rs[0]; }
}

// ---------------- fused attn + S1/S2 partials ----------------
__global__ __launch_bounds__(256) void k_muS(float* __restrict__ outA, int last) {
    int ch = blockIdx.x, b = blockIdx.y;
    int n0 = ch * CR;
    int tid = threadIdx.x;
    __shared__ __align__(16) float sa[CR][K_];
    __shared__ float sm[K_], sd[K_];
    if (tid < K_) { sm[tid] = g_mx[b * K_ + tid]; sd[tid] = g_di[b * K_ + tid]; }
    __syncthreads();
#pragma unroll
    for (int i = 0; i < 2; i++) {
        int idx = tid + i * 256;
        int nl = idx >> 3, k = idx & 7;
        float g = g_gll[((size_t)(b * N_ + n0 + nl)) * K_ + k];
        sa[nl][k] = expf(g - sm[k]) * sd[k];
    }
    __syncthreads();
    if (last && tid < CR) {
#pragma unroll
        for (int k = 0; k < K_; k++)
            outA[((size_t)(b * K_ + k)) * N_ + n0 + tid] = sa[tid][k];
    }
    int d = tid;
    float a1[K_], a2[K_];
#pragma unroll
    for (int k = 0; k < K_; k++) { a1[k] = 0.f; a2[k] = 0.f; }
    const float* vb = g_vals + ((size_t)(b * N_ + n0)) * D_ + d;
#pragma unroll 8
    for (int nl = 0; nl < CR; nl++) {
        float vv = vb[(size_t)nl * D_];
        float v2 = vv * vv;
        float4 p0 = *(const float4*)&sa[nl][0];
        float4 p1 = *(const float4*)&sa[nl][4];
        a1[0] = fmaf(p0.x, vv, a1[0]); a2[0] = fmaf(p0.x, v2, a2[0]);
        a1[1] = fmaf(p0.y, vv, a1[1]); a2[1] = fmaf(p0.y, v2, a2[1]);
        a1[2] = fmaf(p0.z, vv, a1[2]); a2[2] = fmaf(p0.z, v2, a2[2]);
        a1[3] = fmaf(p0.w, vv, a1[3]); a2[3] = fmaf(p0.w, v2, a2[3]);
        a1[4] = fmaf(p1.x, vv, a1[4]); a2[4] = fmaf(p1.x, v2, a2[4]);
        a1[5] = fmaf(p1.y, vv, a1[5]); a2[5] = fmaf(p1.y, v2, a2[5]);
        a1[6] = fmaf(p1.z, vv, a1[6]); a2[6] = fmaf(p1.z, v2, a2[6]);
        a1[7] = fmaf(p1.w, vv, a1[7]); a2[7] = fmaf(p1.w, v2, a2[7]);
    }
#pragma unroll
    for (int k = 0; k < K_; k++) {
        size_t idx = (((size_t)(b * NCH + ch)) * K_ + k) * D_ + d;
        g_p1[idx] = a1[k];
        g_p2[idx] = a2[k];
    }
}

// ------ reduce partials -> mu, sigma; last iter also writes slots_out --------
__global__ void k_redfin(const float* __restrict__ nf, float* __restrict__ out, int last) {
    int k = blockIdx.x, b = blockIdx.y, d = threadIdx.x;
    float s1 = 0.f, s2 = 0.f;
#pragma unroll 8
    for (int c = 0; c < NCH; c++) {
        size_t idx = (((size_t)(b * NCH + c)) * K_ + k) * D_ + d;
        s1 += g_p1[idx];
        s2 += g_p2[idx];
    }
    int o = (b * K_ + k) * D_ + d;
    float sig = fmaf(-s1, s1, s2);
    g_mu[o]  = s1;
    g_sig[o] = sig;
    if (last) out[o] = s1 + fmaxf(fabsf(sig), 1e-8f) * nf[o];
}

// ---------------------------------------------------------------------------
extern "C" void kernel_launch(void* const* d_in, const int* in_sizes, int n_in,
                              void* d_out, int out_size) {
    const float* emb  = (const float*)d_in[0];
    const float* smu  = (const float*)d_in[1];
    const float* sls  = (const float*)d_in[2];
    const float* Wq   = (const float*)d_in[4];
    const float* Wk   = (const float*)d_in[5];
    const float* Wv   = (const float*)d_in[6];
    const float* lnsc = (const float*)d_in[7];
    const float* lnb  = (const float*)d_in[8];
    const float* ni   = (const float*)d_in[9];
    const float* nf   = (const float*)d_in[10];
    float* out      = (float*)d_out;
    float* out_attn = out + B_ * K_ * D_;

    static int smem_set = 0;
    if (!smem_set) {
        cudaFuncSetAttribute(k_gemm_mma, cudaFuncAttributeMaxDynamicSharedMemorySize, GEMM_SMEM);
        smem_set = 1;
    }

    k_lnstats<<<N_ * B_ / 8, 256>>>(emb);
    k_gemm_mma<<<dim3(256, 4), 256, GEMM_SMEM>>>(emb, lnsc, lnb, Wk, Wv);
    k_setup<<<B_ * K_, 256>>>(smu, sls, ni, Wq);

    for (int it = 0; it < 3; it++) {
        int last = (it == 2) ? 1 : 0;
        k_gll<<<dim3(N_ / 32, B_), 256>>>();
        k_comb<<<B_ * K_, 128>>>();
        k_muS<<<dim3(NCH, B_), 256>>>(out_attn, last);
        k_redfin<<<dim3(K_, B_), 256>>>(nf, out, last);
    }
}

// round 16
// speedup vs baseline: 1.9332x; 1.0072x over previous
#include <cuda_runtime.h>
#include <cuda_bf16.h>
#include <math.h>

typedef unsigned int u32;

#define B_  8
#define N_  4096
#define K_  8
#define D_  256
#define NCH 64
#define CR  64
#define NBLK 64
#define LOGCONST (-235.24826450320013f)

// ---------------- scratch ----------------
__device__ float2 g_lnst[B_ * N_];
__device__ float  g_keys[B_ * N_ * D_];
__device__ float  g_vals[B_ * N_ * D_];
__device__ float  g_gll [B_ * N_ * K_];
__device__ float  g_q   [B_ * K_ * D_];
__device__ float  g_sig [B_ * K_ * D_];
__device__ float2 g_suw [B_ * K_ * D_];
__device__ float  g_c1  [B_ * K_];
__device__ float  g_bmax[B_ * K_ * NBLK];
__device__ float  g_bsum[B_ * K_ * NBLK];
__device__ float  g_p1  [B_ * NCH * K_ * D_];
__device__ float  g_p2  [B_ * NCH * K_ * D_];

__device__ __forceinline__ u32 smem_u32(const void* p) {
    u32 a;
    asm("{ .reg .u64 t; cvta.to.shared.u64 t, %1; cvt.u32.u64 %0, t; }" : "=r"(a) : "l"(p));
    return a;
}

// ---------------- LayerNorm row stats ----------------
__global__ void k_lnstats(const float* __restrict__ emb) {
    int warp = threadIdx.x >> 5, lane = threadIdx.x & 31;
    int row  = blockIdx.x * 8 + warp;
    const float* base = emb + (size_t)row * D_;
    float s = 0.f, sq = 0.f;
#pragma unroll
    for (int j = 0; j < 8; j++) {
        float v = base[lane + 32 * j];
        s += v;
        sq = fmaf(v, v, sq);
    }
#pragma unroll
    for (int o = 16; o; o >>= 1) {
        s  += __shfl_xor_sync(0xffffffffu, s,  o);
        sq += __shfl_xor_sync(0xffffffffu, sq, o);
    }
    if (lane == 0) {
        float mean = s * (1.0f / D_);
        float var  = sq * (1.0f / D_) - mean * mean;
        g_lnst[row] = make_float2(mean, 1.0f / sqrtf(var + 1e-5f));
    }
}

// ===== bf16x3 GEMM: mma.m16n8k16 + ldmatrix, double-buffered (proven) =====
__device__ __forceinline__ void mma16(float* c, const u32* a, u32 b0, u32 b1) {
    asm volatile(
        "mma.sync.aligned.m16n8k16.row.col.f32.bf16.bf16.f32 "
        "{%0,%1,%2,%3}, {%4,%5,%6,%7}, {%8,%9}, {%0,%1,%2,%3};"
        : "+f"(c[0]), "+f"(c[1]), "+f"(c[2]), "+f"(c[3])
        : "r"(a[0]), "r"(a[1]), "r"(a[2]), "r"(a[3]), "r"(b0), "r"(b1));
}
#define LDSM_X4(r, addr) \
    asm volatile("ldmatrix.sync.aligned.m8n8.x4.shared.b16 {%0,%1,%2,%3}, [%4];" \
        : "=r"((r)[0]), "=r"((r)[1]), "=r"((r)[2]), "=r"((r)[3]) : "r"(addr))

__device__ __forceinline__ u32 packbf(float a, float b) {
    __nv_bfloat162 v = __floats2bfloat162_rn(a, b);
    return *(u32*)&v;
}

#define ROWB 80
#define PLANE 10240
#define BUFB  (4 * PLANE)
#define GEMM_SMEM (2 * BUFB)

__global__ __launch_bounds__(256, 1) void k_gemm_mma(const float* __restrict__ emb,
                                                     const float* __restrict__ lnsc,
                                                     const float* __restrict__ lnb,
                                                     const float* __restrict__ Wk,
                                                     const float* __restrict__ Wv) {
    extern __shared__ char smc[];
    const u32 sb = smem_u32(smc);
    const int tid = threadIdx.x, lane = tid & 31, wid = tid >> 5;
    const int m0 = blockIdx.x * 128;
    const int nq = blockIdx.y;
    const float* Bsrc = (nq < 2) ? Wk : Wv;
    float* outp = (nq < 2) ? g_keys : g_vals;
    const int n0 = (nq & 1) * 128;
    const int wm = wid >> 2, wn = wid & 3;
    const int g = lane >> 2, tt = lane & 3;

    const int aRow = tid >> 3;
    const int sg   = (tid & 7) * 4;

    float2 st[4];
#pragma unroll
    for (int i = 0; i < 4; i++) st[i] = g_lnst[m0 + aRow + 32 * i];

    float4 ra[4], rb[4], rsc, rbi;

    float acc[4][4][4];
#pragma unroll
    for (int i = 0; i < 4; i++)
#pragma unroll
        for (int j = 0; j < 4; j++)
#pragma unroll
            for (int r = 0; r < 4; r++) acc[i][j][r] = 0.f;

    auto ldgs = [&](int kc) {
        const int k0 = kc * 32;
#pragma unroll
        for (int i = 0; i < 4; i++) {
            ra[i] = *(const float4*)&emb [(size_t)(m0 + aRow + 32 * i) * D_ + k0 + sg];
            rb[i] = *(const float4*)&Bsrc[(size_t)(n0 + aRow + 32 * i) * D_ + k0 + sg];
        }
        rsc = *(const float4*)&lnsc[k0 + sg];
        rbi = *(const float4*)&lnb [k0 + sg];
    };

    auto cvst = [&](int buf) {
        char* Ah = smc + buf * BUFB;
        char* Am = Ah + PLANE;
        char* Bh = Ah + 2 * PLANE;
        char* Bm = Ah + 3 * PLANE;
#pragma unroll
        for (int i = 0; i < 4; i++) {
            int off = (aRow + 32 * i) * ROWB + sg * 2;
            float x0 = fmaf((ra[i].x - st[i].x) * st[i].y, rsc.x, rbi.x);
            float x1 = fmaf((ra[i].y - st[i].x) * st[i].y, rsc.y, rbi.y);
            float x2 = fmaf((ra[i].z - st[i].x) * st[i].y, rsc.z, rbi.z);
            float x3 = fmaf((ra[i].w - st[i].x) * st[i].y, rsc.w, rbi.w);
            u32 h01 = packbf(x0, x1), h23 = packbf(x2, x3);
            float m0f = x0 - __uint_as_float(h01 << 16);
            float m1f = x1 - __uint_as_float(h01 & 0xffff0000u);
            float m2f = x2 - __uint_as_float(h23 << 16);
            float m3f = x3 - __uint_as_float(h23 & 0xffff0000u);
            *(uint2*)(Ah + off) = make_uint2(h01, h23);
            *(uint2*)(Am + off) = make_uint2(packbf(m0f, m1f), packbf(m2f, m3f));
            u32 g01 = packbf(rb[i].x, rb[i].y), g23 = packbf(rb[i].z, rb[i].w);
            float n0f = rb[i].x - __uint_as_float(g01 << 16);
            float n1f = rb[i].y - __uint_as_float(g01 & 0xffff0000u);
            float n2f = rb[i].z - __uint_as_float(g23 << 16);
            float n3f = rb[i].w - __uint_as_float(g23 & 0xffff0000u);
            *(uint2*)(Bh + off) = make_uint2(g01, g23);
            *(uint2*)(Bm + off) = make_uint2(packbf(n0f, n1f), packbf(n2f, n3f));
        }
    };

    const u32 laneoff = ((lane & 7) + (lane & 8)) * ROWB + ((lane & 16) ? 16 : 0);

    auto mmab = [&](int buf) {
        const u32 base = sb + buf * BUFB;
#pragma unroll
        for (int ks = 0; ks < 2; ks++) {
            const u32 kb = ks * 32;
            u32 ah[4][4], am[4][4], bh[2][4], bm[2][4];
#pragma unroll
            for (int mt = 0; mt < 4; mt++) {
                u32 addr = base + (u32)(wm * 64 + mt * 16) * ROWB + kb + laneoff;
                LDSM_X4(ah[mt], addr);
                LDSM_X4(am[mt], addr + PLANE);
            }
#pragma unroll
            for (int np = 0; np < 2; np++) {
                u32 addr = base + 2 * PLANE + (u32)(wn * 32 + np * 16) * ROWB + kb + laneoff;
                LDSM_X4(bh[np], addr);
                LDSM_X4(bm[np], addr + PLANE);
            }
#pragma unroll
            for (int mt = 0; mt < 4; mt++)
#pragma unroll
                for (int nt = 0; nt < 4; nt++) {
                    int np = nt >> 1, sl = nt & 1;
                    mma16(acc[mt][nt], ah[mt], bh[np][sl], bh[np][sl + 2]);
                    mma16(acc[mt][nt], ah[mt], bm[np][sl], bm[np][sl + 2]);
                    mma16(acc[mt][nt], am[mt], bh[np][sl], bh[np][sl + 2]);
                }
        }
    };

    ldgs(0);
    cvst(0);
    __syncthreads();
    for (int kc = 0; kc < 8; kc++) {
        if (kc < 7) ldgs(kc + 1);
        mmab(kc & 1);
        if (kc < 7) cvst((kc + 1) & 1);
        __syncthreads();
    }

#pragma unroll
    for (int mt = 0; mt < 4; mt++) {
        int r = m0 + wm * 64 + mt * 16;
#pragma unroll
        for (int nt = 0; nt < 4; nt++) {
            int c = n0 + wn * 32 + nt * 8 + 2 * tt;
            *(float2*)&outp[(size_t)(r + g    ) * D_ + c] = make_float2(acc[mt][nt][0], acc[mt][nt][1]);
            *(float2*)&outp[(size_t)(r + g + 8) * D_ + c] = make_float2(acc[mt][nt][2], acc[mt][nt][3]);
        }
    }
}

// ---------------- setup: sigma init + queries ----------------
__global__ __launch_bounds__(256) void k_setup(const float* __restrict__ smu,
                                               const float* __restrict__ sls,
                                               const float* __restrict__ ni,
                                               const float* __restrict__ Wq) {
    int bk = blockIdx.x;
    int b = bk >> 3, k = bk & 7;
    int tid = threadIdx.x, wid = tid >> 5, lane = tid & 31;
    __shared__ float ss[D_];
    float sg   = expf(sls[k * D_ + tid]);
    float slot = smu[k * D_ + tid] + sg * ni[(b * K_ + k) * D_ + tid];
    ss[tid] = slot;
    g_sig[(b * K_ + k) * D_ + tid] = sg;
    __syncthreads();
    for (int j = 0; j < 32; j++) {
        int d = wid * 32 + j;
        const float* wr = Wq + (size_t)d * D_;
        float s = 0.f;
#pragma unroll
        for (int c = 0; c < 8; c++) s = fmaf(wr[lane + 32 * c], ss[lane + 32 * c], s);
#pragma unroll
        for (int o = 16; o; o >>= 1) s += __shfl_xor_sync(0xffffffffu, s, o);
        if (lane == 0) g_q[(b * K_ + k) * D_ + d] = s;
    }
}

// ---- shared prep tail: sig,q -> suw + c1 (block = one (b,k), 256 thr) ------
__device__ __forceinline__ void prep_tail(int b, int k, int tid, float sig, float q) {
    int o = (b * K_ + k) * D_ + tid;
    int wid = tid >> 5, lane = tid & 31;
    float w = 1.0f / fmaf(sig, sig, 1e-8f);
    g_suw[o] = make_float2(q * w, -0.5f * w);
    float loc = logf(fabsf(sig) + 1e-8f) + q * q * w;
    __shared__ float ws[8];
#pragma unroll
    for (int of = 16; of; of >>= 1) loc += __shfl_xor_sync(0xffffffffu, loc, of);
    if (lane == 0) ws[wid] = loc;
    __syncthreads();
    if (tid == 0) {
        float s = 0.f;
#pragma unroll
        for (int j = 0; j < 8; j++) s += ws[j];
        g_c1[b * K_ + k] = LOGCONST - 0.5f * s;
    }
}

// ---------------- prep0: iteration-0 suw/c1 from setup's sig,q ----------------
__global__ __launch_bounds__(256) void k_prep0() {
    int k = blockIdx.x, b = blockIdx.y, tid = threadIdx.x;
    int o = (b * K_ + k) * D_ + tid;
    prep_tail(b, k, tid, g_sig[o], g_q[o]);
}

// ------- gll: 512 thr / 64 rows; table-copy prologue; softmax partials -------
__global__ __launch_bounds__(512) void k_gll() {
    const int b  = blockIdx.y;
    const int n0 = blockIdx.x * 64;
    const int tid = threadIdx.x;
    const int wid = tid >> 5, lane = tid & 31;
    __shared__ float2 suw[K_ * D_];
    __shared__ float sc1[K_];
    __shared__ float sgv[64][K_];
    const float2* gs = g_suw + (size_t)b * K_ * D_;
#pragma unroll
    for (int i = 0; i < 2; i++) {
        int e = tid + i * 512;                     // 0..1023, 2 float2 each
        *(float4*)&suw[e * 2] = *(const float4*)&gs[e * 2];
    }
    if (tid < K_) sc1[tid] = g_c1[b * K_ + tid];
    __syncthreads();

    const float* kr = g_keys + ((size_t)(b * N_ + n0 + wid * 4)) * D_;
    float acc[4][K_];
#pragma unroll
    for (int r = 0; r < 4; r++)
#pragma unroll
        for (int k = 0; k < K_; k++) acc[r][k] = 0.f;

#pragma unroll
    for (int j = 0; j < 8; j++) {
        int dd = lane + 32 * j;
        float v0 = kr[dd];
        float v1 = kr[D_ + dd];
        float v2 = kr[2 * D_ + dd];
        float v3 = kr[3 * D_ + dd];
        float q0 = v0 * v0, q1 = v1 * v1, q2 = v2 * v2, q3 = v3 * v3;
#pragma unroll
        for (int k = 0; k < K_; k++) {
            float2 uw = suw[k * D_ + dd];
            acc[0][k] = fmaf(v0, uw.x, fmaf(q0, uw.y, acc[0][k]));
            acc[1][k] = fmaf(v1, uw.x, fmaf(q1, uw.y, acc[1][k]));
            acc[2][k] = fmaf(v2, uw.x, fmaf(q2, uw.y, acc[2][k]));
            acc[3][k] = fmaf(v3, uw.x, fmaf(q3, uw.y, acc[3][k]));
        }
    }
#pragma unroll
    for (int r = 0; r < 4; r++) {
#pragma unroll
        for (int o = 16; o; o >>= 1)
#pragma unroll
            for (int k = 0; k < K_; k++) acc[r][k] += __shfl_xor_sync(0xffffffffu, acc[r][k], o);
        if (lane == 0) {
            int n = n0 + wid * 4 + r;
#pragma unroll
            for (int k = 0; k < K_; k++) {
                float g = sc1[k] + acc[r][k];
                g = fminf(fmaxf(g, -10000.f), 10000.f);
                g_gll[((size_t)(b * N_ + n)) * K_ + k] = g;
                sgv[wid * 4 + r][k] = g;
            }
        }
    }
    __syncthreads();
    if (tid < K_) {
        float m = -3.4e38f;
#pragma unroll
        for (int i = 0; i < 64; i++) m = fmaxf(m, sgv[i][tid]);
        float s = 0.f;
#pragma unroll
        for (int i = 0; i < 64; i++) s += expf(sgv[i][tid] - m);
        g_bmax[(b * K_ + tid) * NBLK + blockIdx.x] = m;
        g_bsum[(b * K_ + tid) * NBLK + blockIdx.x] = s;
    }
}

// -------- fused (inline comb) attn + S1/S2 partials ----------
__global__ __launch_bounds__(256) void k_muS(float* __restrict__ outA, int last) {
    int ch = blockIdx.x, b = blockIdx.y;
    int n0 = ch * CR;
    int tid = threadIdx.x;
    int wid = tid >> 5, lane = tid & 31;
    __shared__ __align__(16) float sa[CR][K_];
    __shared__ float sm[K_], sd[K_];
    // inline comb: warp w handles k=w over NBLK=64 partials
    {
        int base = (b * K_ + wid) * NBLK;
        float m0 = g_bmax[base + lane];
        float m1 = g_bmax[base + 32 + lane];
        float s0 = g_bsum[base + lane];
        float s1 = g_bsum[base + 32 + lane];
        float mm = fmaxf(m0, m1);
#pragma unroll
        for (int o = 16; o; o >>= 1) mm = fmaxf(mm, __shfl_xor_sync(0xffffffffu, mm, o));
        float ss = s0 * expf(m0 - mm) + s1 * expf(m1 - mm);
#pragma unroll
        for (int o = 16; o; o >>= 1) ss += __shfl_xor_sync(0xffffffffu, ss, o);
        if (lane == 0) { sm[wid] = mm; sd[wid] = 1.0f / ss; }
    }
    __syncthreads();
#pragma unroll
    for (int i = 0; i < 2; i++) {
        int idx = tid + i * 256;
        int nl = idx >> 3, k = idx & 7;
        float g = g_gll[((size_t)(b * N_ + n0 + nl)) * K_ + k];
        sa[nl][k] = expf(g - sm[k]) * sd[k];
    }
    __syncthreads();
    if (last && tid < CR) {
#pragma unroll
        for (int k = 0; k < K_; k++)
            outA[((size_t)(b * K_ + k)) * N_ + n0 + tid] = sa[tid][k];
    }
    int d = tid;
    float a1[K_], a2[K_];
#pragma unroll
    for (int k = 0; k < K_; k++) { a1[k] = 0.f; a2[k] = 0.f; }
    const float* vb = g_vals + ((size_t)(b * N_ + n0)) * D_ + d;
#pragma unroll 8
    for (int nl = 0; nl < CR; nl++) {
        float vv = vb[(size_t)nl * D_];
        float v2 = vv * vv;
        float4 p0 = *(const float4*)&sa[nl][0];
        float4 p1 = *(const float4*)&sa[nl][4];
        a1[0] = fmaf(p0.x, vv, a1[0]); a2[0] = fmaf(p0.x, v2, a2[0]);
        a1[1] = fmaf(p0.y, vv, a1[1]); a2[1] = fmaf(p0.y, v2, a2[1]);
        a1[2] = fmaf(p0.z, vv, a1[2]); a2[2] = fmaf(p0.z, v2, a2[2]);
        a1[3] = fmaf(p0.w, vv, a1[3]); a2[3] = fmaf(p0.w, v2, a2[3]);
        a1[4] = fmaf(p1.x, vv, a1[4]); a2[4] = fmaf(p1.x, v2, a2[4]);
        a1[5] = fmaf(p1.y, vv, a1[5]); a2[5] = fmaf(p1.y, v2, a2[5]);
        a1[6] = fmaf(p1.z, vv, a1[6]); a2[6] = fmaf(p1.z, v2, a2[6]);
        a1[7] = fmaf(p1.w, vv, a1[7]); a2[7] = fmaf(p1.w, v2, a2[7]);
    }
#pragma unroll
    for (int k = 0; k < K_; k++) {
        size_t idx = (((size_t)(b * NCH + ch)) * K_ + k) * D_ + d;
        g_p1[idx] = a1[k];
        g_p2[idx] = a2[k];
    }
}

// ------ redfin: reduce partials; prep next iter (suw,c1) or write output -----
__global__ __launch_bounds__(256) void k_redfin(const float* __restrict__ nf,
                                                float* __restrict__ out, int last) {
    int k = blockIdx.x, b = blockIdx.y, tid = threadIdx.x;
    float s1 = 0.f, s2 = 0.f;
#pragma unroll 8
    for (int c = 0; c < NCH; c++) {
        size_t idx = (((size_t)(b * NCH + c)) * K_ + k) * D_ + tid;
        s1 += g_p1[idx];
        s2 += g_p2[idx];
    }
    float sig = fmaf(-s1, s1, s2);
    if (last) {
        int o = (b * K_ + k) * D_ + tid;
        out[o] = s1 + fmaxf(fabsf(sig), 1e-8f) * nf[o];
    } else {
        float q = g_q[(b * K_ + k) * D_ + tid];
        prep_tail(b, k, tid, sig, q);
    }
}

// ---------------------------------------------------------------------------
extern "C" void kernel_launch(void* const* d_in, const int* in_sizes, int n_in,
                              void* d_out, int out_size) {
    const float* emb  = (const float*)d_in[0];
    const float* smu  = (const float*)d_in[1];
    const float* sls  = (const float*)d_in[2];
    const float* Wq   = (const float*)d_in[4];
    const float* Wk   = (const float*)d_in[5];
    const float* Wv   = (const float*)d_in[6];
    const float* lnsc = (const float*)d_in[7];
    const float* lnb  = (const float*)d_in[8];
    const float* ni   = (const float*)d_in[9];
    const float* nf   = (const float*)d_in[10];
    float* out      = (float*)d_out;
    float* out_attn = out + B_ * K_ * D_;

    static int smem_set = 0;
    if (!smem_set) {
        cudaFuncSetAttribute(k_gemm_mma, cudaFuncAttributeMaxDynamicSharedMemorySize, GEMM_SMEM);
        smem_set = 1;
    }

    k_lnstats<<<N_ * B_ / 8, 256>>>(emb);
    k_gemm_mma<<<dim3(256, 4), 256, GEMM_SMEM>>>(emb, lnsc, lnb, Wk, Wv);
    k_setup<<<B_ * K_, 256>>>(smu, sls, ni, Wq);
    k_prep0<<<dim3(K_, B_), 256>>>();

    for (int it = 0; it < 3; it++) {
        int last = (it == 2) ? 1 : 0;
        k_gll<<<dim3(N_ / 64, B_), 512>>>();
        k_muS<<<dim3(NCH, B_), 256>>>(out_attn, last);
        k_redfin<<<dim3(K_, B_), 256>>>(nf, out, last);
    }
}